// round 4
// baseline (speedup 1.0000x reference)
#include <cuda_runtime.h>
#include <math.h>
#include <stdint.h>

#define Bsz   4
#define Nseq  2048
#define Dm    512
#define Hh    8
#define HDim  64
#define MLPH  2048
#define ROWS  (Bsz * Nseq)
#define SCALE 0.125f

// ---------------- scratch ----------------
__device__ float g_h[ROWS * Dm];
__device__ float g_qkv[ROWS * 3 * Dm];
__device__ float g_attn[ROWS * Dm];
__device__ float g_x1[ROWS * Dm];
__device__ float g_act[ROWS * MLPH];
__device__ float g_wt[3145728];
#define WT_QKV  0
#define WT_PROJ 786432
#define WT_FC1  1048576
#define WT_FC2  2097152

// ---------------- helpers ----------------
__device__ __forceinline__ uint32_t cvt_tf32(float x) {
    uint32_t r; asm("cvt.rna.tf32.f32 %0, %1;" : "=r"(r) : "f"(x)); return r;
}
__device__ __forceinline__ float round_tf32(float x) {
    return __uint_as_float(cvt_tf32(x));
}
__device__ __forceinline__ uint32_t smem_u32(const void* p) {
    return (uint32_t)__cvta_generic_to_shared(p);
}
__device__ __forceinline__ void ldsm4(uint32_t r[4], uint32_t a) {
    asm volatile("ldmatrix.sync.aligned.m8n8.x4.shared.b16 {%0,%1,%2,%3}, [%4];"
        : "=r"(r[0]), "=r"(r[1]), "=r"(r[2]), "=r"(r[3]) : "r"(a));
}
__device__ __forceinline__ void mma8(float d[4], const uint32_t a[4],
                                     uint32_t b0, uint32_t b1) {
    asm volatile(
        "mma.sync.aligned.m16n8k8.row.col.f32.tf32.tf32.f32 "
        "{%0,%1,%2,%3}, {%4,%5,%6,%7}, {%8,%9}, {%0,%1,%2,%3};"
        : "+f"(d[0]), "+f"(d[1]), "+f"(d[2]), "+f"(d[3])
        : "r"(a[0]), "r"(a[1]), "r"(a[2]), "r"(a[3]), "r"(b0), "r"(b1));
}
__device__ __forceinline__ void cpa16(uint32_t dst, const void* src) {
    asm volatile("cp.async.cg.shared.global [%0], [%1], 16;\n"
        :: "r"(dst), "l"(src));
}
#define CP_COMMIT() asm volatile("cp.async.commit_group;\n" ::: "memory")
#define CP_WAIT1()  asm volatile("cp.async.wait_group 1;\n" ::: "memory")
#define CP_WAIT0()  asm volatile("cp.async.wait_group 0;\n" ::: "memory")

// ---------------- weight transpose + tf32 round ----------------
__global__ __launch_bounds__(256) void transpose_cvt(
    const float* __restrict__ in, float* __restrict__ out, int K, int N)
{
    __shared__ float t[32][33];
    int n0 = blockIdx.x * 32, k0 = blockIdx.y * 32;
    int tx = threadIdx.x, ty = threadIdx.y;
    #pragma unroll
    for (int j = 0; j < 32; j += 8)
        t[ty + j][tx] = in[(size_t)(k0 + ty + j) * N + n0 + tx];
    __syncthreads();
    #pragma unroll
    for (int j = 0; j < 32; j += 8)
        out[(size_t)(n0 + ty + j) * K + k0 + tx] = round_tf32(t[tx][ty + j]);
}

// ---------------- LayerNorm (tf32-rounded output) ----------------
__global__ __launch_bounds__(128) void ln_kernel(
    const float* __restrict__ in, const float* __restrict__ gamma,
    const float* __restrict__ beta, float* __restrict__ out)
{
    int row = blockIdx.x;
    int tid = threadIdx.x;
    const float4* p = (const float4*)(in + (size_t)row * Dm);
    float4 v = p[tid];
    float s  = v.x + v.y + v.z + v.w;
    float ss = v.x * v.x + v.y * v.y + v.z * v.z + v.w * v.w;
    #pragma unroll
    for (int o = 16; o; o >>= 1) {
        s  += __shfl_xor_sync(0xffffffffu, s,  o);
        ss += __shfl_xor_sync(0xffffffffu, ss, o);
    }
    __shared__ float sm[8];
    int w = tid >> 5, lane = tid & 31;
    if (lane == 0) { sm[w] = s; sm[4 + w] = ss; }
    __syncthreads();
    float tot  = sm[0] + sm[1] + sm[2] + sm[3];
    float tot2 = sm[4] + sm[5] + sm[6] + sm[7];
    float mean = tot * (1.0f / Dm);
    float var  = tot2 * (1.0f / Dm) - mean * mean;
    float inv  = rsqrtf(var + 1e-5f);
    float4 g4 = ((const float4*)gamma)[tid];
    float4 b4 = ((const float4*)beta)[tid];
    float4 o;
    o.x = round_tf32((v.x - mean) * inv * g4.x + b4.x);
    o.y = round_tf32((v.y - mean) * inv * g4.y + b4.y);
    o.z = round_tf32((v.z - mean) * inv * g4.z + b4.z);
    o.w = round_tf32((v.w - mean) * inv * g4.w + b4.w);
    ((float4*)(out + (size_t)row * Dm))[tid] = o;
}

// ---------------- TF32 GEMM (unchanged from R3) ----------------
#define STG_B 8192
#define BOFF  24576

__device__ __forceinline__ float gelu_exact(float x) {
    return 0.5f * x * (1.0f + erff(x * 0.70710678118654752f));
}

template<int N, int K, bool BIAS, bool GELU, bool RES, bool ROUND>
__global__ __launch_bounds__(256, 2) void tgemm(
    const float* __restrict__ A, const float* __restrict__ WT,
    const float* __restrict__ bias, const float* __restrict__ res,
    float* __restrict__ C)
{
    __shared__ uint32_t smbuf[12288];
    uint32_t smb = smem_u32(smbuf);

    int tid = threadIdx.x, lane = tid & 31, warp = tid >> 5;
    int brow = blockIdx.y * 128, bcol = blockIdx.x * 128;
    int wm = (warp >> 1) * 32, wn = (warp & 1) * 64;
    int la = lane & 7, grp = lane >> 3, g = lane >> 2, t = lane & 3;

    int m0 = tid >> 2, t4 = tid & 3;
    const float* Ag0 = A  + (size_t)(brow + m0) * K + t4 * 4;
    const float* Ag1 = Ag0 + (size_t)64 * K;
    const float* Bg0 = WT + (size_t)(bcol + m0) * K + t4 * 4;
    const float* Bg1 = Bg0 + (size_t)64 * K;
    uint32_t dA0 = smb + (uint32_t)(m0 * 16 + ((t4 ^ ((m0 >> 1) & 3)) << 2)) * 4u;
    uint32_t dA1 = dA0 + 4096;
    uint32_t dB0 = dA0 + BOFF;
    uint32_t dB1 = dB0 + 4096;

    uint32_t aAddr[2];
    #pragma unroll
    for (int mi = 0; mi < 2; mi++) {
        int r = wm + mi * 16 + la + (grp & 1) * 8;
        int c = grp >> 1;
        int ph = c ^ ((r >> 1) & 3);
        aAddr[mi] = smb + (uint32_t)(r * 64 + (ph << 4));
    }
    uint32_t bAddr;
    {
        int n = wn + (lane & 7) + ((lane >> 4) & 1) * 8;
        int c = (lane >> 3) & 1;
        int ph = c ^ ((n >> 1) & 3);
        bAddr = smb + BOFF + (uint32_t)(n * 64 + (ph << 4));
    }

    float acc[2][8][4];
    #pragma unroll
    for (int mi = 0; mi < 2; mi++)
        #pragma unroll
        for (int ni = 0; ni < 8; ni++)
            #pragma unroll
            for (int c = 0; c < 4; c++) acc[mi][ni][c] = 0.0f;

    constexpr int iters = K / 16;

    #pragma unroll
    for (int p = 0; p < 2; p++) {
        uint32_t o = p * STG_B;
        size_t ko = (size_t)p * 16;
        cpa16(dA0 + o, Ag0 + ko); cpa16(dA1 + o, Ag1 + ko);
        cpa16(dB0 + o, Bg0 + ko); cpa16(dB1 + o, Bg1 + ko);
        CP_COMMIT();
    }

    #pragma unroll 1
    for (int it = 0; it < iters; ++it) {
        CP_WAIT1();
        __syncthreads();
        if (it + 2 < iters) {
            int sp = (it + 2) % 3;
            uint32_t o = sp * STG_B;
            size_t ko = (size_t)(it + 2) * 16;
            cpa16(dA0 + o, Ag0 + ko); cpa16(dA1 + o, Ag1 + ko);
            cpa16(dB0 + o, Bg0 + ko); cpa16(dB1 + o, Bg1 + ko);
        }
        CP_COMMIT();

        uint32_t so = (uint32_t)((it % 3) * STG_B);
        #pragma unroll
        for (int ks = 0; ks < 2; ks++) {
            uint32_t kx = (uint32_t)(ks << 5);
            uint32_t af0[4], af1[4];
            ldsm4(af0, (aAddr[0] + so) ^ kx);
            ldsm4(af1, (aAddr[1] + so) ^ kx);
            #pragma unroll
            for (int ng = 0; ng < 4; ng++) {
                uint32_t bf[4];
                ldsm4(bf, (bAddr + so + ng * 1024) ^ kx);
                mma8(acc[0][ng * 2],     af0, bf[0], bf[1]);
                mma8(acc[0][ng * 2 + 1], af0, bf[2], bf[3]);
                mma8(acc[1][ng * 2],     af1, bf[0], bf[1]);
                mma8(acc[1][ng * 2 + 1], af1, bf[2], bf[3]);
            }
        }
    }

    #pragma unroll
    for (int mi = 0; mi < 2; mi++) {
        int r0 = brow + wm + mi * 16 + g;
        #pragma unroll
        for (int ni = 0; ni < 8; ni++) {
            int col = bcol + wn + ni * 8 + t * 2;
            float2 v0 = {acc[mi][ni][0], acc[mi][ni][1]};
            float2 v1 = {acc[mi][ni][2], acc[mi][ni][3]};
            if (BIAS) {
                float2 bb = *(const float2*)&bias[col];
                v0.x += bb.x; v0.y += bb.y; v1.x += bb.x; v1.y += bb.y;
            }
            if (GELU) {
                v0.x = gelu_exact(v0.x); v0.y = gelu_exact(v0.y);
                v1.x = gelu_exact(v1.x); v1.y = gelu_exact(v1.y);
            }
            if (RES) {
                float2 q0 = *(const float2*)&res[(size_t)r0 * N + col];
                float2 q1 = *(const float2*)&res[(size_t)(r0 + 8) * N + col];
                v0.x += q0.x; v0.y += q0.y; v1.x += q1.x; v1.y += q1.y;
            }
            if (ROUND) {
                v0.x = round_tf32(v0.x); v0.y = round_tf32(v0.y);
                v1.x = round_tf32(v1.x); v1.y = round_tf32(v1.y);
            }
            *(float2*)&C[(size_t)r0 * N + col] = v0;
            *(float2*)&C[(size_t)(r0 + 8) * N + col] = v1;
        }
    }
}

// ---------------- TF32 flash attention v2 ----------------
// 128 q-rows/block, 256 thr (8 warps x 16 rows), cp.async double-buffered K/V.
// Dynamic smem (words): QP[128*68] | K[2][64*68] | V[2][64*68] | EK[2][64]
#define KPW      68
#define OFF_QP   0
#define OFF_K    8704
#define OFF_V    17408
#define OFF_EK   26112
#define ATT_WORDS 26240
#define ATT_BYTES (ATT_WORDS * 4)
#define KVSTG    4352          // words per K or V buffer

__device__ __forceinline__ float bias_f(float eq, float ek, float alpha) {
    float diff = (ek - eq) * 1e-3f;
    float b = -alpha * fmaxf(diff, 0.0f);
    return fminf(fmaxf(b, -10.0f), 0.0f);
}

__global__ __launch_bounds__(256, 1) void attn_tc(
    const float* __restrict__ qkv, const float* __restrict__ elev,
    const float* __restrict__ alpha_p, float* __restrict__ out)
{
    extern __shared__ uint32_t dsm[];
    uint32_t smb = smem_u32(dsm);
    float* sEK = (float*)(dsm + OFF_EK);

    int b = blockIdx.y >> 3, h = blockIdx.y & 7;
    int q0 = blockIdx.x * 128;
    int tid = threadIdx.x, lane = tid & 31, warp = tid >> 5;
    int la = lane & 7, grp = lane >> 3, g = lane >> 2, t = lane & 3;
    float alpha = alpha_p[0];
    const float* eb = elev + b * Nseq;
    const float* qbase = qkv + ((size_t)(b * Nseq + q0)) * (3 * Dm) + h * HDim;
    const float* kvb   = qkv + ((size_t)(b * Nseq)) * (3 * Dm) + Dm + h * HDim;

    // prologue: stage Q (2048 chunks) + K/V tile 0 (1024 chunks each)
    #pragma unroll
    for (int i = 0; i < 8; i++) {
        int idx = tid + i * 256;
        int r = idx >> 4, c4 = (idx & 15) * 4;
        cpa16(smb + (uint32_t)(OFF_QP + r * KPW + c4) * 4u,
              qbase + (size_t)r * (3 * Dm) + c4);
    }
    #pragma unroll
    for (int i = 0; i < 4; i++) {
        int idx = tid + i * 256;
        int r = idx >> 4, c4 = (idx & 15) * 4;
        const float* src = kvb + (size_t)r * (3 * Dm) + c4;
        cpa16(smb + (uint32_t)(OFF_K + r * KPW + c4) * 4u, src);
        cpa16(smb + (uint32_t)(OFF_V + r * KPW + c4) * 4u, src + Dm);
    }
    if (tid < 64) sEK[tid] = eb[tid];
    CP_COMMIT();
    CP_WAIT0();
    __syncthreads();

    int qr0 = warp * 16;
    uint32_t aAddr = smb +
        (uint32_t)(OFF_QP + (qr0 + la + (grp & 1) * 8) * KPW + (grp >> 1) * 4) * 4u;
    uint32_t qf[8][4];
    #pragma unroll
    for (int kc = 0; kc < 8; kc++) ldsm4(qf[kc], aAddr + kc * 32);

    float eq0 = eb[q0 + qr0 + g];
    float eq1 = eb[q0 + qr0 + g + 8];

    uint32_t bAddrK[4];
    #pragma unroll
    for (int nt = 0; nt < 4; nt++) {
        int r = nt * 16 + la + (grp >> 1) * 8;
        bAddrK[nt] = smb + (uint32_t)(OFF_K + r * KPW + (grp & 1) * 4) * 4u;
    }

    float O[8][4];
    #pragma unroll
    for (int e = 0; e < 8; e++)
        O[e][0] = O[e][1] = O[e][2] = O[e][3] = 0.0f;
    float mi0 = -1e30f, mi1 = -1e30f, li0 = 0.0f, li1 = 0.0f;

    #pragma unroll 1
    for (int tt = 0; tt < Nseq / 64; tt++) {
        if (tt) { CP_WAIT0(); __syncthreads(); }
        if (tt + 1 < Nseq / 64) {
            int bufn = (tt + 1) & 1;
            const float* kb = kvb + (size_t)(tt + 1) * 64 * (3 * Dm);
            #pragma unroll
            for (int i = 0; i < 4; i++) {
                int idx = tid + i * 256;
                int r = idx >> 4, c4 = (idx & 15) * 4;
                const float* src = kb + (size_t)r * (3 * Dm) + c4;
                cpa16(smb + (uint32_t)(OFF_K + bufn * KVSTG + r * KPW + c4) * 4u, src);
                cpa16(smb + (uint32_t)(OFF_V + bufn * KVSTG + r * KPW + c4) * 4u, src + Dm);
            }
            if (tid < 64) sEK[bufn * 64 + tid] = eb[(tt + 1) * 64 + tid];
        }
        CP_COMMIT();

        int buf = tt & 1;
        uint32_t kOff = (uint32_t)(buf * KVSTG) * 4u;

        float S[8][4];
        #pragma unroll
        for (int nt = 0; nt < 8; nt++)
            S[nt][0] = S[nt][1] = S[nt][2] = S[nt][3] = 0.0f;
        #pragma unroll
        for (int kc = 0; kc < 8; kc++) {
            #pragma unroll
            for (int nt4 = 0; nt4 < 4; nt4++) {
                uint32_t bf[4];
                ldsm4(bf, bAddrK[nt4] + kOff + kc * 32);
                mma8(S[nt4 * 2], qf[kc], bf[0], bf[1]);
                mma8(S[nt4 * 2 + 1], qf[kc], bf[2], bf[3]);
            }
        }

        float rm0 = -1e30f, rm1 = -1e30f;
        #pragma unroll
        for (int nt = 0; nt < 8; nt++) {
            float ek0 = sEK[buf * 64 + nt * 8 + t * 2];
            float ek1 = sEK[buf * 64 + nt * 8 + t * 2 + 1];
            S[nt][0] = S[nt][0] * SCALE + bias_f(eq0, ek0, alpha);
            S[nt][1] = S[nt][1] * SCALE + bias_f(eq0, ek1, alpha);
            S[nt][2] = S[nt][2] * SCALE + bias_f(eq1, ek0, alpha);
            S[nt][3] = S[nt][3] * SCALE + bias_f(eq1, ek1, alpha);
            rm0 = fmaxf(rm0, fmaxf(S[nt][0], S[nt][1]));
            rm1 = fmaxf(rm1, fmaxf(S[nt][2], S[nt][3]));
        }
        rm0 = fmaxf(rm0, __shfl_xor_sync(0xffffffffu, rm0, 1));
        rm0 = fmaxf(rm0, __shfl_xor_sync(0xffffffffu, rm0, 2));
        rm1 = fmaxf(rm1, __shfl_xor_sync(0xffffffffu, rm1, 1));
        rm1 = fmaxf(rm1, __shfl_xor_sync(0xffffffffu, rm1, 2));
        float mn0 = fmaxf(mi0, rm0), mn1 = fmaxf(mi1, rm1);
        float c0 = __expf(mi0 - mn0), c1 = __expf(mi1 - mn1);
        mi0 = mn0; mi1 = mn1;
        float rs0 = 0.0f, rs1 = 0.0f;
        #pragma unroll
        for (int nt = 0; nt < 8; nt++) {
            S[nt][0] = __expf(S[nt][0] - mn0); rs0 += S[nt][0];
            S[nt][1] = __expf(S[nt][1] - mn0); rs0 += S[nt][1];
            S[nt][2] = __expf(S[nt][2] - mn1); rs1 += S[nt][2];
            S[nt][3] = __expf(S[nt][3] - mn1); rs1 += S[nt][3];
        }
        rs0 += __shfl_xor_sync(0xffffffffu, rs0, 1);
        rs0 += __shfl_xor_sync(0xffffffffu, rs0, 2);
        rs1 += __shfl_xor_sync(0xffffffffu, rs1, 1);
        rs1 += __shfl_xor_sync(0xffffffffu, rs1, 2);
        li0 = li0 * c0 + rs0;
        li1 = li1 * c1 + rs1;
        #pragma unroll
        for (int e = 0; e < 8; e++) {
            O[e][0] *= c0; O[e][1] *= c0; O[e][2] *= c1; O[e][3] *= c1;
        }

        // P into own 16 rows of QP region (warp-private; no block sync needed)
        #pragma unroll
        for (int nt = 0; nt < 8; nt++) {
            uint32_t* p0 = &dsm[OFF_QP + (qr0 + g) * KPW + nt * 8 + t * 2];
            uint32_t* p1 = &dsm[OFF_QP + (qr0 + 8 + g) * KPW + nt * 8 + t * 2];
            p0[0] = cvt_tf32(S[nt][0]); p0[1] = cvt_tf32(S[nt][1]);
            p1[0] = cvt_tf32(S[nt][2]); p1[1] = cvt_tf32(S[nt][3]);
        }
        __syncwarp();

        #pragma unroll
        for (int kc = 0; kc < 8; kc++) {
            uint32_t pf[4];
            ldsm4(pf, aAddr + kc * 32);
            const uint32_t* v0 = &dsm[OFF_V + buf * KVSTG + (kc * 8 + t) * KPW + g];
            const uint32_t* v1 = v0 + 4 * KPW;
            #pragma unroll
            for (int e = 0; e < 8; e++)
                mma8(O[e], pf, v0[e * 8], v1[e * 8]);
        }
    }

    float inv0 = 1.0f / li0, inv1 = 1.0f / li1;
    int row0 = b * Nseq + q0 + qr0 + g;
    #pragma unroll
    for (int e = 0; e < 8; e++) {
        int col = h * HDim + e * 8 + t * 2;
        float2 o0 = {round_tf32(O[e][0] * inv0), round_tf32(O[e][1] * inv0)};
        float2 o1 = {round_tf32(O[e][2] * inv1), round_tf32(O[e][3] * inv1)};
        *(float2*)&out[(size_t)row0 * Dm + col] = o0;
        *(float2*)&out[(size_t)(row0 + 8) * Dm + col] = o1;
    }
}

// ---------------- launch ----------------
extern "C" void kernel_launch(void* const* d_in, const int* in_sizes, int n_in,
                              void* d_out, int out_size)
{
    const float* x     = (const float*)d_in[0];
    const float* elev  = (const float*)d_in[1];
    const float* ln1g  = (const float*)d_in[2];
    const float* ln1b  = (const float*)d_in[3];
    const float* qkvw  = (const float*)d_in[4];
    const float* alpha = (const float*)d_in[5];
    const float* projw = (const float*)d_in[6];
    const float* projb = (const float*)d_in[7];
    const float* ln2g  = (const float*)d_in[8];
    const float* ln2b  = (const float*)d_in[9];
    const float* fc1w  = (const float*)d_in[10];
    const float* fc1b  = (const float*)d_in[11];
    const float* fc2w  = (const float*)d_in[12];
    const float* fc2b  = (const float*)d_in[13];
    float* out = (float*)d_out;

    float *ph, *pqkv, *pattn, *px1, *pact, *pwt;
    cudaGetSymbolAddress((void**)&ph,    g_h);
    cudaGetSymbolAddress((void**)&pqkv,  g_qkv);
    cudaGetSymbolAddress((void**)&pattn, g_attn);
    cudaGetSymbolAddress((void**)&px1,   g_x1);
    cudaGetSymbolAddress((void**)&pact,  g_act);
    cudaGetSymbolAddress((void**)&pwt,   g_wt);

    cudaFuncSetAttribute(attn_tc,
        cudaFuncAttributeMaxDynamicSharedMemorySize, ATT_BYTES);

    // 0. weight transpose + tf32 round
    transpose_cvt<<<dim3(48, 16), dim3(32, 8)>>>(qkvw,  pwt + WT_QKV,  Dm,   3 * Dm);
    transpose_cvt<<<dim3(16, 16), dim3(32, 8)>>>(projw, pwt + WT_PROJ, Dm,   Dm);
    transpose_cvt<<<dim3(64, 16), dim3(32, 8)>>>(fc1w,  pwt + WT_FC1,  Dm,   MLPH);
    transpose_cvt<<<dim3(16, 64), dim3(32, 8)>>>(fc2w,  pwt + WT_FC2,  MLPH, Dm);

    // 1. LN1
    ln_kernel<<<ROWS, 128>>>(x, ln1g, ln1b, ph);
    // 2. qkv = h @ qkv_w  (ROUND=true: Q/K/V pre-rounded for attention)
    tgemm<1536, 512, false, false, false, true><<<dim3(12, 64), 256>>>(
        ph, pwt + WT_QKV, nullptr, nullptr, pqkv);
    // 3. attention
    attn_tc<<<dim3(Nseq / 128, Bsz * Hh), 256, ATT_BYTES>>>(pqkv, elev, alpha, pattn);
    // 4. x1 = x + attn @ proj_w + proj_b
    tgemm<512, 512, true, false, true, false><<<dim3(4, 64), 256>>>(
        pattn, pwt + WT_PROJ, projb, x, px1);
    // 5. LN2
    ln_kernel<<<ROWS, 128>>>(px1, ln2g, ln2b, ph);
    // 6. act = gelu(h2 @ fc1_w + fc1_b)
    tgemm<2048, 512, true, true, false, true><<<dim3(16, 64), 256>>>(
        ph, pwt + WT_FC1, fc1b, nullptr, pact);
    // 7. out = x1 + act @ fc2_w + fc2_b
    tgemm<512, 2048, true, false, true, false><<<dim3(4, 64), 256>>>(
        pact, pwt + WT_FC2, fc2b, px1, out);
}

// round 5
// speedup vs baseline: 1.0852x; 1.0852x over previous
#include <cuda_runtime.h>
#include <math.h>
#include <stdint.h>

#define Bsz   4
#define Nseq  2048
#define Dm    512
#define Hh    8
#define HDim  64
#define MLPH  2048
#define ROWS  (Bsz * Nseq)
#define SCALE 0.125f

// ---------------- scratch ----------------
__device__ float g_h[ROWS * Dm];
__device__ float g_qkv[ROWS * 3 * Dm];
__device__ float g_attn[ROWS * Dm];
__device__ float g_x1[ROWS * Dm];
__device__ float g_act[ROWS * MLPH];
__device__ float g_wt[3145728];
#define WT_QKV  0
#define WT_PROJ 786432
#define WT_FC1  1048576
#define WT_FC2  2097152

// ---------------- helpers ----------------
__device__ __forceinline__ uint32_t cvt_tf32(float x) {
    uint32_t r; asm("cvt.rna.tf32.f32 %0, %1;" : "=r"(r) : "f"(x)); return r;
}
__device__ __forceinline__ float round_tf32(float x) {
    return __uint_as_float(cvt_tf32(x));
}
__device__ __forceinline__ uint32_t smem_u32(const void* p) {
    return (uint32_t)__cvta_generic_to_shared(p);
}
__device__ __forceinline__ void ldsm4(uint32_t r[4], uint32_t a) {
    asm volatile("ldmatrix.sync.aligned.m8n8.x4.shared.b16 {%0,%1,%2,%3}, [%4];"
        : "=r"(r[0]), "=r"(r[1]), "=r"(r[2]), "=r"(r[3]) : "r"(a));
}
__device__ __forceinline__ void mma8(float d[4], const uint32_t a[4],
                                     uint32_t b0, uint32_t b1) {
    asm volatile(
        "mma.sync.aligned.m16n8k8.row.col.f32.tf32.tf32.f32 "
        "{%0,%1,%2,%3}, {%4,%5,%6,%7}, {%8,%9}, {%0,%1,%2,%3};"
        : "+f"(d[0]), "+f"(d[1]), "+f"(d[2]), "+f"(d[3])
        : "r"(a[0]), "r"(a[1]), "r"(a[2]), "r"(a[3]), "r"(b0), "r"(b1));
}
__device__ __forceinline__ void cpa16(uint32_t dst, const void* src) {
    asm volatile("cp.async.cg.shared.global [%0], [%1], 16;\n"
        :: "r"(dst), "l"(src));
}
#define CP_COMMIT() asm volatile("cp.async.commit_group;\n" ::: "memory")
#define CP_WAIT1()  asm volatile("cp.async.wait_group 1;\n" ::: "memory")
#define CP_WAIT0()  asm volatile("cp.async.wait_group 0;\n" ::: "memory")

// ---------------- weight transpose + tf32 round ----------------
__global__ __launch_bounds__(256) void transpose_cvt(
    const float* __restrict__ in, float* __restrict__ out, int K, int N)
{
    __shared__ float t[32][33];
    int n0 = blockIdx.x * 32, k0 = blockIdx.y * 32;
    int tx = threadIdx.x, ty = threadIdx.y;
    #pragma unroll
    for (int j = 0; j < 32; j += 8)
        t[ty + j][tx] = in[(size_t)(k0 + ty + j) * N + n0 + tx];
    __syncthreads();
    #pragma unroll
    for (int j = 0; j < 32; j += 8)
        out[(size_t)(n0 + ty + j) * K + k0 + tx] = round_tf32(t[tx][ty + j]);
}

// ---------------- LayerNorm (tf32-rounded output) ----------------
__global__ __launch_bounds__(128) void ln_kernel(
    const float* __restrict__ in, const float* __restrict__ gamma,
    const float* __restrict__ beta, float* __restrict__ out)
{
    int row = blockIdx.x;
    int tid = threadIdx.x;
    const float4* p = (const float4*)(in + (size_t)row * Dm);
    float4 v = p[tid];
    float s  = v.x + v.y + v.z + v.w;
    float ss = v.x * v.x + v.y * v.y + v.z * v.z + v.w * v.w;
    #pragma unroll
    for (int o = 16; o; o >>= 1) {
        s  += __shfl_xor_sync(0xffffffffu, s,  o);
        ss += __shfl_xor_sync(0xffffffffu, ss, o);
    }
    __shared__ float sm[8];
    int w = tid >> 5, lane = tid & 31;
    if (lane == 0) { sm[w] = s; sm[4 + w] = ss; }
    __syncthreads();
    float tot  = sm[0] + sm[1] + sm[2] + sm[3];
    float tot2 = sm[4] + sm[5] + sm[6] + sm[7];
    float mean = tot * (1.0f / Dm);
    float var  = tot2 * (1.0f / Dm) - mean * mean;
    float inv  = rsqrtf(var + 1e-5f);
    float4 g4 = ((const float4*)gamma)[tid];
    float4 b4 = ((const float4*)beta)[tid];
    float4 o;
    o.x = round_tf32((v.x - mean) * inv * g4.x + b4.x);
    o.y = round_tf32((v.y - mean) * inv * g4.y + b4.y);
    o.z = round_tf32((v.z - mean) * inv * g4.z + b4.z);
    o.w = round_tf32((v.w - mean) * inv * g4.w + b4.w);
    ((float4*)(out + (size_t)row * Dm))[tid] = o;
}

// ---------------- TF32 GEMM (unchanged) ----------------
#define STG_B 8192
#define BOFF  24576

__device__ __forceinline__ float gelu_exact(float x) {
    return 0.5f * x * (1.0f + erff(x * 0.70710678118654752f));
}

template<int N, int K, bool BIAS, bool GELU, bool RES, bool ROUND>
__global__ __launch_bounds__(256, 2) void tgemm(
    const float* __restrict__ A, const float* __restrict__ WT,
    const float* __restrict__ bias, const float* __restrict__ res,
    float* __restrict__ C)
{
    __shared__ uint32_t smbuf[12288];
    uint32_t smb = smem_u32(smbuf);

    int tid = threadIdx.x, lane = tid & 31, warp = tid >> 5;
    int brow = blockIdx.y * 128, bcol = blockIdx.x * 128;
    int wm = (warp >> 1) * 32, wn = (warp & 1) * 64;
    int la = lane & 7, grp = lane >> 3, g = lane >> 2, t = lane & 3;

    int m0 = tid >> 2, t4 = tid & 3;
    const float* Ag0 = A  + (size_t)(brow + m0) * K + t4 * 4;
    const float* Ag1 = Ag0 + (size_t)64 * K;
    const float* Bg0 = WT + (size_t)(bcol + m0) * K + t4 * 4;
    const float* Bg1 = Bg0 + (size_t)64 * K;
    uint32_t dA0 = smb + (uint32_t)(m0 * 16 + ((t4 ^ ((m0 >> 1) & 3)) << 2)) * 4u;
    uint32_t dA1 = dA0 + 4096;
    uint32_t dB0 = dA0 + BOFF;
    uint32_t dB1 = dB0 + 4096;

    uint32_t aAddr[2];
    #pragma unroll
    for (int mi = 0; mi < 2; mi++) {
        int r = wm + mi * 16 + la + (grp & 1) * 8;
        int c = grp >> 1;
        int ph = c ^ ((r >> 1) & 3);
        aAddr[mi] = smb + (uint32_t)(r * 64 + (ph << 4));
    }
    uint32_t bAddr;
    {
        int n = wn + (lane & 7) + ((lane >> 4) & 1) * 8;
        int c = (lane >> 3) & 1;
        int ph = c ^ ((n >> 1) & 3);
        bAddr = smb + BOFF + (uint32_t)(n * 64 + (ph << 4));
    }

    float acc[2][8][4];
    #pragma unroll
    for (int mi = 0; mi < 2; mi++)
        #pragma unroll
        for (int ni = 0; ni < 8; ni++)
            #pragma unroll
            for (int c = 0; c < 4; c++) acc[mi][ni][c] = 0.0f;

    constexpr int iters = K / 16;

    #pragma unroll
    for (int p = 0; p < 2; p++) {
        uint32_t o = p * STG_B;
        size_t ko = (size_t)p * 16;
        cpa16(dA0 + o, Ag0 + ko); cpa16(dA1 + o, Ag1 + ko);
        cpa16(dB0 + o, Bg0 + ko); cpa16(dB1 + o, Bg1 + ko);
        CP_COMMIT();
    }

    #pragma unroll 1
    for (int it = 0; it < iters; ++it) {
        CP_WAIT1();
        __syncthreads();
        if (it + 2 < iters) {
            int sp = (it + 2) % 3;
            uint32_t o = sp * STG_B;
            size_t ko = (size_t)(it + 2) * 16;
            cpa16(dA0 + o, Ag0 + ko); cpa16(dA1 + o, Ag1 + ko);
            cpa16(dB0 + o, Bg0 + ko); cpa16(dB1 + o, Bg1 + ko);
        }
        CP_COMMIT();

        uint32_t so = (uint32_t)((it % 3) * STG_B);
        #pragma unroll
        for (int ks = 0; ks < 2; ks++) {
            uint32_t kx = (uint32_t)(ks << 5);
            uint32_t af0[4], af1[4];
            ldsm4(af0, (aAddr[0] + so) ^ kx);
            ldsm4(af1, (aAddr[1] + so) ^ kx);
            #pragma unroll
            for (int ng = 0; ng < 4; ng++) {
                uint32_t bf[4];
                ldsm4(bf, (bAddr + so + ng * 1024) ^ kx);
                mma8(acc[0][ng * 2],     af0, bf[0], bf[1]);
                mma8(acc[0][ng * 2 + 1], af0, bf[2], bf[3]);
                mma8(acc[1][ng * 2],     af1, bf[0], bf[1]);
                mma8(acc[1][ng * 2 + 1], af1, bf[2], bf[3]);
            }
        }
    }

    #pragma unroll
    for (int mi = 0; mi < 2; mi++) {
        int r0 = brow + wm + mi * 16 + g;
        #pragma unroll
        for (int ni = 0; ni < 8; ni++) {
            int col = bcol + wn + ni * 8 + t * 2;
            float2 v0 = {acc[mi][ni][0], acc[mi][ni][1]};
            float2 v1 = {acc[mi][ni][2], acc[mi][ni][3]};
            if (BIAS) {
                float2 bb = *(const float2*)&bias[col];
                v0.x += bb.x; v0.y += bb.y; v1.x += bb.x; v1.y += bb.y;
            }
            if (GELU) {
                v0.x = gelu_exact(v0.x); v0.y = gelu_exact(v0.y);
                v1.x = gelu_exact(v1.x); v1.y = gelu_exact(v1.y);
            }
            if (RES) {
                float2 q0 = *(const float2*)&res[(size_t)r0 * N + col];
                float2 q1 = *(const float2*)&res[(size_t)(r0 + 8) * N + col];
                v0.x += q0.x; v0.y += q0.y; v1.x += q1.x; v1.y += q1.y;
            }
            if (ROUND) {
                v0.x = round_tf32(v0.x); v0.y = round_tf32(v0.y);
                v1.x = round_tf32(v1.x); v1.y = round_tf32(v1.y);
            }
            *(float2*)&C[(size_t)r0 * N + col] = v0;
            *(float2*)&C[(size_t)(r0 + 8) * N + col] = v1;
        }
    }
}

// ---------------- TF32 flash attention v2.1 (occupancy 2) ----------------
#define KPW      68
#define OFF_QP   0
#define OFF_K    8704
#define OFF_V    17408
#define OFF_EK   26112
#define ATT_WORDS 26240
#define ATT_BYTES (ATT_WORDS * 4)
#define KVSTG    4352

__device__ __forceinline__ float bias_f(float eq, float ek, float alpha) {
    float diff = (ek - eq) * 1e-3f;
    float b = -alpha * fmaxf(diff, 0.0f);
    return fminf(fmaxf(b, -10.0f), 0.0f);
}

__global__ __launch_bounds__(256, 2) void attn_tc(
    const float* __restrict__ qkv, const float* __restrict__ elev,
    const float* __restrict__ alpha_p, float* __restrict__ out)
{
    extern __shared__ uint32_t dsm[];
    uint32_t smb = smem_u32(dsm);
    float* sEK = (float*)(dsm + OFF_EK);

    int b = blockIdx.y >> 3, h = blockIdx.y & 7;
    int q0 = blockIdx.x * 128;
    int tid = threadIdx.x, lane = tid & 31, warp = tid >> 5;
    int la = lane & 7, grp = lane >> 3, g = lane >> 2, t = lane & 3;
    float alpha = alpha_p[0];
    const float* eb = elev + b * Nseq;
    const float* qbase = qkv + ((size_t)(b * Nseq + q0)) * (3 * Dm) + h * HDim;
    const float* kvb   = qkv + ((size_t)(b * Nseq)) * (3 * Dm) + Dm + h * HDim;

    #pragma unroll
    for (int i = 0; i < 8; i++) {
        int idx = tid + i * 256;
        int r = idx >> 4, c4 = (idx & 15) * 4;
        cpa16(smb + (uint32_t)(OFF_QP + r * KPW + c4) * 4u,
              qbase + (size_t)r * (3 * Dm) + c4);
    }
    #pragma unroll
    for (int i = 0; i < 4; i++) {
        int idx = tid + i * 256;
        int r = idx >> 4, c4 = (idx & 15) * 4;
        const float* src = kvb + (size_t)r * (3 * Dm) + c4;
        cpa16(smb + (uint32_t)(OFF_K + r * KPW + c4) * 4u, src);
        cpa16(smb + (uint32_t)(OFF_V + r * KPW + c4) * 4u, src + Dm);
    }
    if (tid < 64) sEK[tid] = eb[tid];
    CP_COMMIT();
    CP_WAIT0();
    __syncthreads();

    int qr0 = warp * 16;
    uint32_t aAddr = smb +
        (uint32_t)(OFF_QP + (qr0 + la + (grp & 1) * 8) * KPW + (grp >> 1) * 4) * 4u;
    uint32_t qf[8][4];
    #pragma unroll
    for (int kc = 0; kc < 8; kc++) ldsm4(qf[kc], aAddr + kc * 32);

    float eq0 = eb[q0 + qr0 + g];
    float eq1 = eb[q0 + qr0 + g + 8];

    uint32_t bAddrK[4];
    #pragma unroll
    for (int nt = 0; nt < 4; nt++) {
        int r = nt * 16 + la + (grp >> 1) * 8;
        bAddrK[nt] = smb + (uint32_t)(OFF_K + r * KPW + (grp & 1) * 4) * 4u;
    }

    float O[8][4];
    #pragma unroll
    for (int e = 0; e < 8; e++)
        O[e][0] = O[e][1] = O[e][2] = O[e][3] = 0.0f;
    float mi0 = -1e30f, mi1 = -1e30f, li0 = 0.0f, li1 = 0.0f;

    #pragma unroll 1
    for (int tt = 0; tt < Nseq / 64; tt++) {
        if (tt) { CP_WAIT0(); __syncthreads(); }
        if (tt + 1 < Nseq / 64) {
            int bufn = (tt + 1) & 1;
            const float* kb = kvb + (size_t)(tt + 1) * 64 * (3 * Dm);
            #pragma unroll
            for (int i = 0; i < 4; i++) {
                int idx = tid + i * 256;
                int r = idx >> 4, c4 = (idx & 15) * 4;
                const float* src = kb + (size_t)r * (3 * Dm) + c4;
                cpa16(smb + (uint32_t)(OFF_K + bufn * KVSTG + r * KPW + c4) * 4u, src);
                cpa16(smb + (uint32_t)(OFF_V + bufn * KVSTG + r * KPW + c4) * 4u, src + Dm);
            }
            if (tid < 64) sEK[bufn * 64 + tid] = eb[(tt + 1) * 64 + tid];
        }
        CP_COMMIT();

        int buf = tt & 1;
        uint32_t kOff = (uint32_t)(buf * KVSTG) * 4u;

        float S[8][4];
        #pragma unroll
        for (int nt = 0; nt < 8; nt++)
            S[nt][0] = S[nt][1] = S[nt][2] = S[nt][3] = 0.0f;
        #pragma unroll
        for (int kc = 0; kc < 8; kc++) {
            #pragma unroll
            for (int nt4 = 0; nt4 < 4; nt4++) {
                uint32_t bf[4];
                ldsm4(bf, bAddrK[nt4] + kOff + kc * 32);
                mma8(S[nt4 * 2], qf[kc], bf[0], bf[1]);
                mma8(S[nt4 * 2 + 1], qf[kc], bf[2], bf[3]);
            }
        }

        float rm0 = -1e30f, rm1 = -1e30f;
        #pragma unroll
        for (int nt = 0; nt < 8; nt++) {
            float ek0 = sEK[buf * 64 + nt * 8 + t * 2];
            float ek1 = sEK[buf * 64 + nt * 8 + t * 2 + 1];
            S[nt][0] = S[nt][0] * SCALE + bias_f(eq0, ek0, alpha);
            S[nt][1] = S[nt][1] * SCALE + bias_f(eq0, ek1, alpha);
            S[nt][2] = S[nt][2] * SCALE + bias_f(eq1, ek0, alpha);
            S[nt][3] = S[nt][3] * SCALE + bias_f(eq1, ek1, alpha);
            rm0 = fmaxf(rm0, fmaxf(S[nt][0], S[nt][1]));
            rm1 = fmaxf(rm1, fmaxf(S[nt][2], S[nt][3]));
        }
        rm0 = fmaxf(rm0, __shfl_xor_sync(0xffffffffu, rm0, 1));
        rm0 = fmaxf(rm0, __shfl_xor_sync(0xffffffffu, rm0, 2));
        rm1 = fmaxf(rm1, __shfl_xor_sync(0xffffffffu, rm1, 1));
        rm1 = fmaxf(rm1, __shfl_xor_sync(0xffffffffu, rm1, 2));
        float mn0 = fmaxf(mi0, rm0), mn1 = fmaxf(mi1, rm1);
        float c0 = __expf(mi0 - mn0), c1 = __expf(mi1 - mn1);
        mi0 = mn0; mi1 = mn1;
        float rs0 = 0.0f, rs1 = 0.0f;
        #pragma unroll
        for (int nt = 0; nt < 8; nt++) {
            S[nt][0] = __expf(S[nt][0] - mn0); rs0 += S[nt][0];
            S[nt][1] = __expf(S[nt][1] - mn0); rs0 += S[nt][1];
            S[nt][2] = __expf(S[nt][2] - mn1); rs1 += S[nt][2];
            S[nt][3] = __expf(S[nt][3] - mn1); rs1 += S[nt][3];
        }
        rs0 += __shfl_xor_sync(0xffffffffu, rs0, 1);
        rs0 += __shfl_xor_sync(0xffffffffu, rs0, 2);
        rs1 += __shfl_xor_sync(0xffffffffu, rs1, 1);
        rs1 += __shfl_xor_sync(0xffffffffu, rs1, 2);
        li0 = li0 * c0 + rs0;
        li1 = li1 * c1 + rs1;
        #pragma unroll
        for (int e = 0; e < 8; e++) {
            O[e][0] *= c0; O[e][1] *= c0; O[e][2] *= c1; O[e][3] *= c1;
        }

        #pragma unroll
        for (int nt = 0; nt < 8; nt++) {
            uint32_t* p0 = &dsm[OFF_QP + (qr0 + g) * KPW + nt * 8 + t * 2];
            uint32_t* p1 = &dsm[OFF_QP + (qr0 + 8 + g) * KPW + nt * 8 + t * 2];
            p0[0] = cvt_tf32(S[nt][0]); p0[1] = cvt_tf32(S[nt][1]);
            p1[0] = cvt_tf32(S[nt][2]); p1[1] = cvt_tf32(S[nt][3]);
        }
        __syncwarp();

        #pragma unroll
        for (int kc = 0; kc < 8; kc++) {
            uint32_t pf[4];
            ldsm4(pf, aAddr + kc * 32);
            const uint32_t* v0 = &dsm[OFF_V + buf * KVSTG + (kc * 8 + t) * KPW + g];
            const uint32_t* v1 = v0 + 4 * KPW;
            #pragma unroll
            for (int e = 0; e < 8; e++)
                mma8(O[e], pf, v0[e * 8], v1[e * 8]);
        }
    }

    float inv0 = 1.0f / li0, inv1 = 1.0f / li1;
    int row0 = b * Nseq + q0 + qr0 + g;
    #pragma unroll
    for (int e = 0; e < 8; e++) {
        int col = h * HDim + e * 8 + t * 2;
        float2 o0 = {round_tf32(O[e][0] * inv0), round_tf32(O[e][1] * inv0)};
        float2 o1 = {round_tf32(O[e][2] * inv1), round_tf32(O[e][3] * inv1)};
        *(float2*)&out[(size_t)row0 * Dm + col] = o0;
        *(float2*)&out[(size_t)(row0 + 8) * Dm + col] = o1;
    }
}

// ---------------- launch ----------------
extern "C" void kernel_launch(void* const* d_in, const int* in_sizes, int n_in,
                              void* d_out, int out_size)
{
    const float* x     = (const float*)d_in[0];
    const float* elev  = (const float*)d_in[1];
    const float* ln1g  = (const float*)d_in[2];
    const float* ln1b  = (const float*)d_in[3];
    const float* qkvw  = (const float*)d_in[4];
    const float* alpha = (const float*)d_in[5];
    const float* projw = (const float*)d_in[6];
    const float* projb = (const float*)d_in[7];
    const float* ln2g  = (const float*)d_in[8];
    const float* ln2b  = (const float*)d_in[9];
    const float* fc1w  = (const float*)d_in[10];
    const float* fc1b  = (const float*)d_in[11];
    const float* fc2w  = (const float*)d_in[12];
    const float* fc2b  = (const float*)d_in[13];
    float* out = (float*)d_out;

    float *ph, *pqkv, *pattn, *px1, *pact, *pwt;
    cudaGetSymbolAddress((void**)&ph,    g_h);
    cudaGetSymbolAddress((void**)&pqkv,  g_qkv);
    cudaGetSymbolAddress((void**)&pattn, g_attn);
    cudaGetSymbolAddress((void**)&px1,   g_x1);
    cudaGetSymbolAddress((void**)&pact,  g_act);
    cudaGetSymbolAddress((void**)&pwt,   g_wt);

    cudaFuncSetAttribute(attn_tc,
        cudaFuncAttributeMaxDynamicSharedMemorySize, ATT_BYTES);

    // 0. weight transpose + tf32 round
    transpose_cvt<<<dim3(48, 16), dim3(32, 8)>>>(qkvw,  pwt + WT_QKV,  Dm,   3 * Dm);
    transpose_cvt<<<dim3(16, 16), dim3(32, 8)>>>(projw, pwt + WT_PROJ, Dm,   Dm);
    transpose_cvt<<<dim3(64, 16), dim3(32, 8)>>>(fc1w,  pwt + WT_FC1,  Dm,   MLPH);
    transpose_cvt<<<dim3(16, 64), dim3(32, 8)>>>(fc2w,  pwt + WT_FC2,  MLPH, Dm);

    // 1. LN1
    ln_kernel<<<ROWS, 128>>>(x, ln1g, ln1b, ph);
    // 2. qkv (ROUND=true: Q/K/V pre-rounded for attention)
    tgemm<1536, 512, false, false, false, true><<<dim3(12, 64), 256>>>(
        ph, pwt + WT_QKV, nullptr, nullptr, pqkv);
    // 3. attention
    attn_tc<<<dim3(Nseq / 128, Bsz * Hh), 256, ATT_BYTES>>>(pqkv, elev, alpha, pattn);
    // 4. x1 = x + attn @ proj_w + proj_b
    tgemm<512, 512, true, false, true, false><<<dim3(4, 64), 256>>>(
        pattn, pwt + WT_PROJ, projb, x, px1);
    // 5. LN2
    ln_kernel<<<ROWS, 128>>>(px1, ln2g, ln2b, ph);
    // 6. act = gelu(h2 @ fc1_w + fc1_b)
    tgemm<2048, 512, true, true, false, true><<<dim3(16, 64), 256>>>(
        ph, pwt + WT_FC1, fc1b, nullptr, pact);
    // 7. out = x1 + act @ fc2_w + fc2_b
    tgemm<512, 2048, true, false, true, false><<<dim3(4, 64), 256>>>(
        pact, pwt + WT_FC2, fc2b, px1, out);
}

// round 6
// speedup vs baseline: 1.1463x; 1.0564x over previous
#include <cuda_runtime.h>
#include <math.h>
#include <stdint.h>

#define Bsz   4
#define Nseq  2048
#define Dm    512
#define Hh    8
#define HDim  64
#define MLPH  2048
#define ROWS  (Bsz * Nseq)
#define SCALE 0.125f

// ---------------- scratch ----------------
__device__ float g_h[ROWS * Dm];
__device__ float g_qkv[ROWS * 3 * Dm];
__device__ float g_attn[ROWS * Dm];
__device__ float g_x1[ROWS * Dm];
__device__ float g_act[ROWS * MLPH];
__device__ float g_wt[3145728];
__device__ float g_vT[Bsz * Hh * HDim * Nseq];   // V transposed [bh*64+e][n]
#define WT_QKV  0
#define WT_PROJ 786432
#define WT_FC1  1048576
#define WT_FC2  2097152

// ---------------- helpers ----------------
__device__ __forceinline__ uint32_t cvt_tf32(float x) {
    uint32_t r; asm("cvt.rna.tf32.f32 %0, %1;" : "=r"(r) : "f"(x)); return r;
}
__device__ __forceinline__ float round_tf32(float x) {
    return __uint_as_float(cvt_tf32(x));
}
__device__ __forceinline__ uint32_t smem_u32(const void* p) {
    return (uint32_t)__cvta_generic_to_shared(p);
}
__device__ __forceinline__ void ldsm4(uint32_t r[4], uint32_t a) {
    asm volatile("ldmatrix.sync.aligned.m8n8.x4.shared.b16 {%0,%1,%2,%3}, [%4];"
        : "=r"(r[0]), "=r"(r[1]), "=r"(r[2]), "=r"(r[3]) : "r"(a));
}
__device__ __forceinline__ void mma8(float d[4], const uint32_t a[4],
                                     uint32_t b0, uint32_t b1) {
    asm volatile(
        "mma.sync.aligned.m16n8k8.row.col.f32.tf32.tf32.f32 "
        "{%0,%1,%2,%3}, {%4,%5,%6,%7}, {%8,%9}, {%0,%1,%2,%3};"
        : "+f"(d[0]), "+f"(d[1]), "+f"(d[2]), "+f"(d[3])
        : "r"(a[0]), "r"(a[1]), "r"(a[2]), "r"(a[3]), "r"(b0), "r"(b1));
}
__device__ __forceinline__ void cpa16(uint32_t dst, const void* src) {
    asm volatile("cp.async.cg.shared.global [%0], [%1], 16;\n"
        :: "r"(dst), "l"(src));
}
#define CP_COMMIT() asm volatile("cp.async.commit_group;\n" ::: "memory")
#define CP_WAIT1()  asm volatile("cp.async.wait_group 1;\n" ::: "memory")
#define CP_WAIT0()  asm volatile("cp.async.wait_group 0;\n" ::: "memory")

// ---------------- weight transpose + tf32 round ----------------
__global__ __launch_bounds__(256) void transpose_cvt(
    const float* __restrict__ in, float* __restrict__ out, int K, int N)
{
    __shared__ float t[32][33];
    int n0 = blockIdx.x * 32, k0 = blockIdx.y * 32;
    int tx = threadIdx.x, ty = threadIdx.y;
    #pragma unroll
    for (int j = 0; j < 32; j += 8)
        t[ty + j][tx] = in[(size_t)(k0 + ty + j) * N + n0 + tx];
    __syncthreads();
    #pragma unroll
    for (int j = 0; j < 32; j += 8)
        out[(size_t)(n0 + ty + j) * K + k0 + tx] = round_tf32(t[tx][ty + j]);
}

// ---------------- V transpose: g_qkv V-section -> g_vT ----------------
// grid (64, 2, 32), block (32, 8). per (b,h): [n=2048][e=64] -> [e][n]
__global__ __launch_bounds__(256) void vtrans_kernel(
    const float* __restrict__ qkv, float* __restrict__ vT)
{
    __shared__ float t[32][33];
    int bh = blockIdx.z;
    int b = bh >> 3, h = bh & 7;
    int n0 = blockIdx.x * 32, e0 = blockIdx.y * 32;
    int tx = threadIdx.x, ty = threadIdx.y;
    const float* src = qkv + (size_t)(b * Nseq) * (3 * Dm) + 2 * Dm + h * HDim;
    #pragma unroll
    for (int j = 0; j < 32; j += 8)
        t[ty + j][tx] = src[(size_t)(n0 + ty + j) * (3 * Dm) + e0 + tx];
    __syncthreads();
    #pragma unroll
    for (int j = 0; j < 32; j += 8)
        vT[(size_t)(bh * HDim + e0 + ty + j) * Nseq + n0 + tx] = t[tx][ty + j];
}

// ---------------- LayerNorm (tf32-rounded output) ----------------
__global__ __launch_bounds__(128) void ln_kernel(
    const float* __restrict__ in, const float* __restrict__ gamma,
    const float* __restrict__ beta, float* __restrict__ out)
{
    int row = blockIdx.x;
    int tid = threadIdx.x;
    const float4* p = (const float4*)(in + (size_t)row * Dm);
    float4 v = p[tid];
    float s  = v.x + v.y + v.z + v.w;
    float ss = v.x * v.x + v.y * v.y + v.z * v.z + v.w * v.w;
    #pragma unroll
    for (int o = 16; o; o >>= 1) {
        s  += __shfl_xor_sync(0xffffffffu, s,  o);
        ss += __shfl_xor_sync(0xffffffffu, ss, o);
    }
    __shared__ float sm[8];
    int w = tid >> 5, lane = tid & 31;
    if (lane == 0) { sm[w] = s; sm[4 + w] = ss; }
    __syncthreads();
    float tot  = sm[0] + sm[1] + sm[2] + sm[3];
    float tot2 = sm[4] + sm[5] + sm[6] + sm[7];
    float mean = tot * (1.0f / Dm);
    float var  = tot2 * (1.0f / Dm) - mean * mean;
    float inv  = rsqrtf(var + 1e-5f);
    float4 g4 = ((const float4*)gamma)[tid];
    float4 b4 = ((const float4*)beta)[tid];
    float4 o;
    o.x = round_tf32((v.x - mean) * inv * g4.x + b4.x);
    o.y = round_tf32((v.y - mean) * inv * g4.y + b4.y);
    o.z = round_tf32((v.z - mean) * inv * g4.z + b4.z);
    o.w = round_tf32((v.w - mean) * inv * g4.w + b4.w);
    ((float4*)(out + (size_t)row * Dm))[tid] = o;
}

// ---------------- TF32 GEMM (unchanged) ----------------
#define STG_B 8192
#define BOFF  24576

__device__ __forceinline__ float gelu_exact(float x) {
    return 0.5f * x * (1.0f + erff(x * 0.70710678118654752f));
}

template<int N, int K, bool BIAS, bool GELU, bool RES, bool ROUND>
__global__ __launch_bounds__(256, 2) void tgemm(
    const float* __restrict__ A, const float* __restrict__ WT,
    const float* __restrict__ bias, const float* __restrict__ res,
    float* __restrict__ C)
{
    __shared__ uint32_t smbuf[12288];
    uint32_t smb = smem_u32(smbuf);

    int tid = threadIdx.x, lane = tid & 31, warp = tid >> 5;
    int brow = blockIdx.y * 128, bcol = blockIdx.x * 128;
    int wm = (warp >> 1) * 32, wn = (warp & 1) * 64;
    int la = lane & 7, grp = lane >> 3, g = lane >> 2, t = lane & 3;

    int m0 = tid >> 2, t4 = tid & 3;
    const float* Ag0 = A  + (size_t)(brow + m0) * K + t4 * 4;
    const float* Ag1 = Ag0 + (size_t)64 * K;
    const float* Bg0 = WT + (size_t)(bcol + m0) * K + t4 * 4;
    const float* Bg1 = Bg0 + (size_t)64 * K;
    uint32_t dA0 = smb + (uint32_t)(m0 * 16 + ((t4 ^ ((m0 >> 1) & 3)) << 2)) * 4u;
    uint32_t dA1 = dA0 + 4096;
    uint32_t dB0 = dA0 + BOFF;
    uint32_t dB1 = dB0 + 4096;

    uint32_t aAddr[2];
    #pragma unroll
    for (int mi = 0; mi < 2; mi++) {
        int r = wm + mi * 16 + la + (grp & 1) * 8;
        int c = grp >> 1;
        int ph = c ^ ((r >> 1) & 3);
        aAddr[mi] = smb + (uint32_t)(r * 64 + (ph << 4));
    }
    uint32_t bAddr;
    {
        int n = wn + (lane & 7) + ((lane >> 4) & 1) * 8;
        int c = (lane >> 3) & 1;
        int ph = c ^ ((n >> 1) & 3);
        bAddr = smb + BOFF + (uint32_t)(n * 64 + (ph << 4));
    }

    float acc[2][8][4];
    #pragma unroll
    for (int mi = 0; mi < 2; mi++)
        #pragma unroll
        for (int ni = 0; ni < 8; ni++)
            #pragma unroll
            for (int c = 0; c < 4; c++) acc[mi][ni][c] = 0.0f;

    constexpr int iters = K / 16;

    #pragma unroll
    for (int p = 0; p < 2; p++) {
        uint32_t o = p * STG_B;
        size_t ko = (size_t)p * 16;
        cpa16(dA0 + o, Ag0 + ko); cpa16(dA1 + o, Ag1 + ko);
        cpa16(dB0 + o, Bg0 + ko); cpa16(dB1 + o, Bg1 + ko);
        CP_COMMIT();
    }

    #pragma unroll 1
    for (int it = 0; it < iters; ++it) {
        CP_WAIT1();
        __syncthreads();
        if (it + 2 < iters) {
            int sp = (it + 2) % 3;
            uint32_t o = sp * STG_B;
            size_t ko = (size_t)(it + 2) * 16;
            cpa16(dA0 + o, Ag0 + ko); cpa16(dA1 + o, Ag1 + ko);
            cpa16(dB0 + o, Bg0 + ko); cpa16(dB1 + o, Bg1 + ko);
        }
        CP_COMMIT();

        uint32_t so = (uint32_t)((it % 3) * STG_B);
        #pragma unroll
        for (int ks = 0; ks < 2; ks++) {
            uint32_t kx = (uint32_t)(ks << 5);
            uint32_t af0[4], af1[4];
            ldsm4(af0, (aAddr[0] + so) ^ kx);
            ldsm4(af1, (aAddr[1] + so) ^ kx);
            #pragma unroll
            for (int ng = 0; ng < 4; ng++) {
                uint32_t bf[4];
                ldsm4(bf, (bAddr + so + ng * 1024) ^ kx);
                mma8(acc[0][ng * 2],     af0, bf[0], bf[1]);
                mma8(acc[0][ng * 2 + 1], af0, bf[2], bf[3]);
                mma8(acc[1][ng * 2],     af1, bf[0], bf[1]);
                mma8(acc[1][ng * 2 + 1], af1, bf[2], bf[3]);
            }
        }
    }

    #pragma unroll
    for (int mi = 0; mi < 2; mi++) {
        int r0 = brow + wm + mi * 16 + g;
        #pragma unroll
        for (int ni = 0; ni < 8; ni++) {
            int col = bcol + wn + ni * 8 + t * 2;
            float2 v0 = {acc[mi][ni][0], acc[mi][ni][1]};
            float2 v1 = {acc[mi][ni][2], acc[mi][ni][3]};
            if (BIAS) {
                float2 bb = *(const float2*)&bias[col];
                v0.x += bb.x; v0.y += bb.y; v1.x += bb.x; v1.y += bb.y;
            }
            if (GELU) {
                v0.x = gelu_exact(v0.x); v0.y = gelu_exact(v0.y);
                v1.x = gelu_exact(v1.x); v1.y = gelu_exact(v1.y);
            }
            if (RES) {
                float2 q0 = *(const float2*)&res[(size_t)r0 * N + col];
                float2 q1 = *(const float2*)&res[(size_t)(r0 + 8) * N + col];
                v0.x += q0.x; v0.y += q0.y; v1.x += q1.x; v1.y += q1.y;
            }
            if (ROUND) {
                v0.x = round_tf32(v0.x); v0.y = round_tf32(v0.y);
                v1.x = round_tf32(v1.x); v1.y = round_tf32(v1.y);
            }
            *(float2*)&C[(size_t)r0 * N + col] = v0;
            *(float2*)&C[(size_t)(r0 + 8) * N + col] = v1;
        }
    }
}

// ---------------- TF32 flash attention v3: all-ldmatrix PV ----------------
#define KPW      68
#define OFF_QP   0
#define OFF_K    8704
#define OFF_V    17408
#define OFF_EK   26112
#define ATT_WORDS 26240
#define ATT_BYTES (ATT_WORDS * 4)
#define KVSTG    4352

__device__ __forceinline__ float bias_f(float eq, float ek, float alpha) {
    float diff = (ek - eq) * 1e-3f;
    float b = -alpha * fmaxf(diff, 0.0f);
    return fminf(fmaxf(b, -10.0f), 0.0f);
}

__global__ __launch_bounds__(256, 2) void attn_tc(
    const float* __restrict__ qkv, const float* __restrict__ vT,
    const float* __restrict__ elev, const float* __restrict__ alpha_p,
    float* __restrict__ out)
{
    extern __shared__ uint32_t dsm[];
    uint32_t smb = smem_u32(dsm);
    float* sEK = (float*)(dsm + OFF_EK);

    int bh = blockIdx.y;
    int b = bh >> 3, h = bh & 7;
    int q0 = blockIdx.x * 128;
    int tid = threadIdx.x, lane = tid & 31, warp = tid >> 5;
    int la = lane & 7, grp = lane >> 3, g = lane >> 2, t = lane & 3;
    float alpha = alpha_p[0];
    const float* eb = elev + b * Nseq;
    const float* qbase = qkv + ((size_t)(b * Nseq + q0)) * (3 * Dm) + h * HDim;
    const float* kvb   = qkv + ((size_t)(b * Nseq)) * (3 * Dm) + Dm + h * HDim;
    const float* vtb   = vT + (size_t)(bh * HDim) * Nseq;   // rows e, cols n

    // prologue: stage Q + K/V tile 0
    #pragma unroll
    for (int i = 0; i < 8; i++) {
        int idx = tid + i * 256;
        int r = idx >> 4, c4 = (idx & 15) * 4;
        cpa16(smb + (uint32_t)(OFF_QP + r * KPW + c4) * 4u,
              qbase + (size_t)r * (3 * Dm) + c4);
    }
    #pragma unroll
    for (int i = 0; i < 4; i++) {
        int idx = tid + i * 256;
        int r = idx >> 4, c4 = (idx & 15) * 4;
        cpa16(smb + (uint32_t)(OFF_K + r * KPW + c4) * 4u,
              kvb + (size_t)r * (3 * Dm) + c4);
        cpa16(smb + (uint32_t)(OFF_V + r * KPW + c4) * 4u,
              vtb + (size_t)r * Nseq + c4);
    }
    if (tid < 64) sEK[tid] = eb[tid];
    CP_COMMIT();
    CP_WAIT0();
    __syncthreads();

    int qr0 = warp * 16;
    uint32_t aAddr = smb +
        (uint32_t)(OFF_QP + (qr0 + la + (grp & 1) * 8) * KPW + (grp >> 1) * 4) * 4u;
    uint32_t qf[8][4];
    #pragma unroll
    for (int kc = 0; kc < 8; kc++) ldsm4(qf[kc], aAddr + kc * 32);

    float eq0 = eb[q0 + qr0 + g];
    float eq1 = eb[q0 + qr0 + g + 8];

    // B-fragment ldsm addresses (shared pattern for K rows and V^T rows)
    uint32_t bAddrK[4], bAddrV[4];
    #pragma unroll
    for (int nt = 0; nt < 4; nt++) {
        int r = nt * 16 + la + (grp >> 1) * 8;
        bAddrK[nt] = smb + (uint32_t)(OFF_K + r * KPW + (grp & 1) * 4) * 4u;
        bAddrV[nt] = smb + (uint32_t)(OFF_V + r * KPW + (grp & 1) * 4) * 4u;
    }

    float O[8][4];
    #pragma unroll
    for (int e = 0; e < 8; e++)
        O[e][0] = O[e][1] = O[e][2] = O[e][3] = 0.0f;
    float mi0 = -1e30f, mi1 = -1e30f, li0 = 0.0f, li1 = 0.0f;

    #pragma unroll 1
    for (int tt = 0; tt < Nseq / 64; tt++) {
        if (tt) { CP_WAIT0(); __syncthreads(); }
        if (tt + 1 < Nseq / 64) {
            int bufn = (tt + 1) & 1;
            int k0n = (tt + 1) * 64;
            const float* kb = kvb + (size_t)k0n * (3 * Dm);
            #pragma unroll
            for (int i = 0; i < 4; i++) {
                int idx = tid + i * 256;
                int r = idx >> 4, c4 = (idx & 15) * 4;
                cpa16(smb + (uint32_t)(OFF_K + bufn * KVSTG + r * KPW + c4) * 4u,
                      kb + (size_t)r * (3 * Dm) + c4);
                cpa16(smb + (uint32_t)(OFF_V + bufn * KVSTG + r * KPW + c4) * 4u,
                      vtb + (size_t)r * Nseq + k0n + c4);
            }
            if (tid < 64) sEK[bufn * 64 + tid] = eb[k0n + tid];
        }
        CP_COMMIT();

        int buf = tt & 1;
        uint32_t bOff = (uint32_t)(buf * KVSTG) * 4u;

        // S = Q K^T
        float S[8][4];
        #pragma unroll
        for (int nt = 0; nt < 8; nt++)
            S[nt][0] = S[nt][1] = S[nt][2] = S[nt][3] = 0.0f;
        #pragma unroll
        for (int kc = 0; kc < 8; kc++) {
            #pragma unroll
            for (int nt4 = 0; nt4 < 4; nt4++) {
                uint32_t bf[4];
                ldsm4(bf, bAddrK[nt4] + bOff + kc * 32);
                mma8(S[nt4 * 2], qf[kc], bf[0], bf[1]);
                mma8(S[nt4 * 2 + 1], qf[kc], bf[2], bf[3]);
            }
        }

        // bias + online softmax
        float rm0 = -1e30f, rm1 = -1e30f;
        #pragma unroll
        for (int nt = 0; nt < 8; nt++) {
            float ek0 = sEK[buf * 64 + nt * 8 + t * 2];
            float ek1 = sEK[buf * 64 + nt * 8 + t * 2 + 1];
            S[nt][0] = S[nt][0] * SCALE + bias_f(eq0, ek0, alpha);
            S[nt][1] = S[nt][1] * SCALE + bias_f(eq0, ek1, alpha);
            S[nt][2] = S[nt][2] * SCALE + bias_f(eq1, ek0, alpha);
            S[nt][3] = S[nt][3] * SCALE + bias_f(eq1, ek1, alpha);
            rm0 = fmaxf(rm0, fmaxf(S[nt][0], S[nt][1]));
            rm1 = fmaxf(rm1, fmaxf(S[nt][2], S[nt][3]));
        }
        rm0 = fmaxf(rm0, __shfl_xor_sync(0xffffffffu, rm0, 1));
        rm0 = fmaxf(rm0, __shfl_xor_sync(0xffffffffu, rm0, 2));
        rm1 = fmaxf(rm1, __shfl_xor_sync(0xffffffffu, rm1, 1));
        rm1 = fmaxf(rm1, __shfl_xor_sync(0xffffffffu, rm1, 2));
        float mn0 = fmaxf(mi0, rm0), mn1 = fmaxf(mi1, rm1);
        float c0 = __expf(mi0 - mn0), c1 = __expf(mi1 - mn1);
        mi0 = mn0; mi1 = mn1;
        float rs0 = 0.0f, rs1 = 0.0f;
        #pragma unroll
        for (int nt = 0; nt < 8; nt++) {
            S[nt][0] = __expf(S[nt][0] - mn0); rs0 += S[nt][0];
            S[nt][1] = __expf(S[nt][1] - mn0); rs0 += S[nt][1];
            S[nt][2] = __expf(S[nt][2] - mn1); rs1 += S[nt][2];
            S[nt][3] = __expf(S[nt][3] - mn1); rs1 += S[nt][3];
        }
        rs0 += __shfl_xor_sync(0xffffffffu, rs0, 1);
        rs0 += __shfl_xor_sync(0xffffffffu, rs0, 2);
        rs1 += __shfl_xor_sync(0xffffffffu, rs1, 1);
        rs1 += __shfl_xor_sync(0xffffffffu, rs1, 2);
        li0 = li0 * c0 + rs0;
        li1 = li1 * c1 + rs1;
        #pragma unroll
        for (int e = 0; e < 8; e++) {
            O[e][0] *= c0; O[e][1] *= c0; O[e][2] *= c1; O[e][3] *= c1;
        }

        // P into own 16 rows of QP region (warp-private)
        #pragma unroll
        for (int nt = 0; nt < 8; nt++) {
            uint32_t* p0 = &dsm[OFF_QP + (qr0 + g) * KPW + nt * 8 + t * 2];
            uint32_t* p1 = &dsm[OFF_QP + (qr0 + 8 + g) * KPW + nt * 8 + t * 2];
            p0[0] = cvt_tf32(S[nt][0]); p0[1] = cvt_tf32(S[nt][1]);
            p1[0] = cvt_tf32(S[nt][2]); p1[1] = cvt_tf32(S[nt][3]);
        }
        __syncwarp();

        // O += P @ V  (all-ldmatrix: B fragments from V^T rows)
        #pragma unroll
        for (int kc = 0; kc < 8; kc++) {
            uint32_t pf[4];
            ldsm4(pf, aAddr + kc * 32);
            #pragma unroll
            for (int nt4 = 0; nt4 < 4; nt4++) {
                uint32_t bf[4];
                ldsm4(bf, bAddrV[nt4] + bOff + kc * 32);
                mma8(O[nt4 * 2],     pf, bf[0], bf[1]);
                mma8(O[nt4 * 2 + 1], pf, bf[2], bf[3]);
            }
        }
    }

    float inv0 = 1.0f / li0, inv1 = 1.0f / li1;
    int row0 = b * Nseq + q0 + qr0 + g;
    #pragma unroll
    for (int e = 0; e < 8; e++) {
        int col = h * HDim + e * 8 + t * 2;
        float2 o0 = {round_tf32(O[e][0] * inv0), round_tf32(O[e][1] * inv0)};
        float2 o1 = {round_tf32(O[e][2] * inv1), round_tf32(O[e][3] * inv1)};
        *(float2*)&out[(size_t)row0 * Dm + col] = o0;
        *(float2*)&out[(size_t)(row0 + 8) * Dm + col] = o1;
    }
}

// ---------------- launch ----------------
extern "C" void kernel_launch(void* const* d_in, const int* in_sizes, int n_in,
                              void* d_out, int out_size)
{
    const float* x     = (const float*)d_in[0];
    const float* elev  = (const float*)d_in[1];
    const float* ln1g  = (const float*)d_in[2];
    const float* ln1b  = (const float*)d_in[3];
    const float* qkvw  = (const float*)d_in[4];
    const float* alpha = (const float*)d_in[5];
    const float* projw = (const float*)d_in[6];
    const float* projb = (const float*)d_in[7];
    const float* ln2g  = (const float*)d_in[8];
    const float* ln2b  = (const float*)d_in[9];
    const float* fc1w  = (const float*)d_in[10];
    const float* fc1b  = (const float*)d_in[11];
    const float* fc2w  = (const float*)d_in[12];
    const float* fc2b  = (const float*)d_in[13];
    float* out = (float*)d_out;

    float *ph, *pqkv, *pattn, *px1, *pact, *pwt, *pvt;
    cudaGetSymbolAddress((void**)&ph,    g_h);
    cudaGetSymbolAddress((void**)&pqkv,  g_qkv);
    cudaGetSymbolAddress((void**)&pattn, g_attn);
    cudaGetSymbolAddress((void**)&px1,   g_x1);
    cudaGetSymbolAddress((void**)&pact,  g_act);
    cudaGetSymbolAddress((void**)&pwt,   g_wt);
    cudaGetSymbolAddress((void**)&pvt,   g_vT);

    cudaFuncSetAttribute(attn_tc,
        cudaFuncAttributeMaxDynamicSharedMemorySize, ATT_BYTES);

    // 0. weight transpose + tf32 round
    transpose_cvt<<<dim3(48, 16), dim3(32, 8)>>>(qkvw,  pwt + WT_QKV,  Dm,   3 * Dm);
    transpose_cvt<<<dim3(16, 16), dim3(32, 8)>>>(projw, pwt + WT_PROJ, Dm,   Dm);
    transpose_cvt<<<dim3(64, 16), dim3(32, 8)>>>(fc1w,  pwt + WT_FC1,  Dm,   MLPH);
    transpose_cvt<<<dim3(16, 64), dim3(32, 8)>>>(fc2w,  pwt + WT_FC2,  MLPH, Dm);

    // 1. LN1
    ln_kernel<<<ROWS, 128>>>(x, ln1g, ln1b, ph);
    // 2. qkv (ROUND=true: Q/K/V pre-rounded)
    tgemm<1536, 512, false, false, false, true><<<dim3(12, 64), 256>>>(
        ph, pwt + WT_QKV, nullptr, nullptr, pqkv);
    // 2b. V transpose for attention PV ldmatrix path
    vtrans_kernel<<<dim3(64, 2, 32), dim3(32, 8)>>>(pqkv, pvt);
    // 3. attention
    attn_tc<<<dim3(Nseq / 128, Bsz * Hh), 256, ATT_BYTES>>>(
        pqkv, pvt, elev, alpha, pattn);
    // 4. x1 = x + attn @ proj_w + proj_b
    tgemm<512, 512, true, false, true, false><<<dim3(4, 64), 256>>>(
        pattn, pwt + WT_PROJ, projb, x, px1);
    // 5. LN2
    ln_kernel<<<ROWS, 128>>>(px1, ln2g, ln2b, ph);
    // 6. act = gelu(h2 @ fc1_w + fc1_b)
    tgemm<2048, 512, true, true, false, true><<<dim3(16, 64), 256>>>(
        ph, pwt + WT_FC1, fc1b, nullptr, pact);
    // 7. out = x1 + act @ fc2_w + fc2_b
    tgemm<512, 2048, true, false, true, false><<<dim3(4, 64), 256>>>(
        pact, pwt + WT_FC2, fc2b, px1, out);
}

// round 7
// speedup vs baseline: 1.1690x; 1.0198x over previous
#include <cuda_runtime.h>
#include <math.h>
#include <stdint.h>

#define Bsz   4
#define Nseq  2048
#define Dm    512
#define Hh    8
#define HDim  64
#define MLPH  2048
#define ROWS  (Bsz * Nseq)
#define SCALE 0.125f

// ---------------- scratch ----------------
__device__ float g_h[ROWS * Dm];
__device__ float g_qkv[ROWS * 3 * Dm];
__device__ float g_attn[ROWS * Dm];
__device__ float g_x1[ROWS * Dm];
__device__ float g_act[ROWS * MLPH];
__device__ float g_wt[3145728];
__device__ float g_vT[Bsz * Hh * HDim * Nseq];
#define WT_QKV  0
#define WT_PROJ 786432
#define WT_FC1  1048576
#define WT_FC2  2097152

// ---------------- helpers ----------------
__device__ __forceinline__ uint32_t cvt_tf32(float x) {
    uint32_t r; asm("cvt.rna.tf32.f32 %0, %1;" : "=r"(r) : "f"(x)); return r;
}
__device__ __forceinline__ float round_tf32(float x) {
    return __uint_as_float(cvt_tf32(x));
}
__device__ __forceinline__ uint32_t smem_u32(const void* p) {
    return (uint32_t)__cvta_generic_to_shared(p);
}
__device__ __forceinline__ void ldsm4(uint32_t r[4], uint32_t a) {
    asm volatile("ldmatrix.sync.aligned.m8n8.x4.shared.b16 {%0,%1,%2,%3}, [%4];"
        : "=r"(r[0]), "=r"(r[1]), "=r"(r[2]), "=r"(r[3]) : "r"(a));
}
__device__ __forceinline__ void mma8(float d[4], const uint32_t a[4],
                                     uint32_t b0, uint32_t b1) {
    asm volatile(
        "mma.sync.aligned.m16n8k8.row.col.f32.tf32.tf32.f32 "
        "{%0,%1,%2,%3}, {%4,%5,%6,%7}, {%8,%9}, {%0,%1,%2,%3};"
        : "+f"(d[0]), "+f"(d[1]), "+f"(d[2]), "+f"(d[3])
        : "r"(a[0]), "r"(a[1]), "r"(a[2]), "r"(a[3]), "r"(b0), "r"(b1));
}
__device__ __forceinline__ void cpa16(uint32_t dst, const void* src) {
    asm volatile("cp.async.cg.shared.global [%0], [%1], 16;\n"
        :: "r"(dst), "l"(src));
}
#define CP_COMMIT() asm volatile("cp.async.commit_group;\n" ::: "memory")
#define CP_WAIT1()  asm volatile("cp.async.wait_group 1;\n" ::: "memory")
#define CP_WAIT0()  asm volatile("cp.async.wait_group 0;\n" ::: "memory")

// ---------------- weight transpose + tf32 round ----------------
__global__ __launch_bounds__(256) void transpose_cvt(
    const float* __restrict__ in, float* __restrict__ out, int K, int N)
{
    __shared__ float t[32][33];
    int n0 = blockIdx.x * 32, k0 = blockIdx.y * 32;
    int tx = threadIdx.x, ty = threadIdx.y;
    #pragma unroll
    for (int j = 0; j < 32; j += 8)
        t[ty + j][tx] = in[(size_t)(k0 + ty + j) * N + n0 + tx];
    __syncthreads();
    #pragma unroll
    for (int j = 0; j < 32; j += 8)
        out[(size_t)(n0 + ty + j) * K + k0 + tx] = round_tf32(t[tx][ty + j]);
}

// ---------------- V transpose ----------------
__global__ __launch_bounds__(256) void vtrans_kernel(
    const float* __restrict__ qkv, float* __restrict__ vT)
{
    __shared__ float t[32][33];
    int bh = blockIdx.z;
    int b = bh >> 3, h = bh & 7;
    int n0 = blockIdx.x * 32, e0 = blockIdx.y * 32;
    int tx = threadIdx.x, ty = threadIdx.y;
    const float* src = qkv + (size_t)(b * Nseq) * (3 * Dm) + 2 * Dm + h * HDim;
    #pragma unroll
    for (int j = 0; j < 32; j += 8)
        t[ty + j][tx] = src[(size_t)(n0 + ty + j) * (3 * Dm) + e0 + tx];
    __syncthreads();
    #pragma unroll
    for (int j = 0; j < 32; j += 8)
        vT[(size_t)(bh * HDim + e0 + ty + j) * Nseq + n0 + tx] = t[tx][ty + j];
}

// ---------------- LayerNorm ----------------
__global__ __launch_bounds__(128) void ln_kernel(
    const float* __restrict__ in, const float* __restrict__ gamma,
    const float* __restrict__ beta, float* __restrict__ out)
{
    int row = blockIdx.x;
    int tid = threadIdx.x;
    const float4* p = (const float4*)(in + (size_t)row * Dm);
    float4 v = p[tid];
    float s  = v.x + v.y + v.z + v.w;
    float ss = v.x * v.x + v.y * v.y + v.z * v.z + v.w * v.w;
    #pragma unroll
    for (int o = 16; o; o >>= 1) {
        s  += __shfl_xor_sync(0xffffffffu, s,  o);
        ss += __shfl_xor_sync(0xffffffffu, ss, o);
    }
    __shared__ float sm[8];
    int w = tid >> 5, lane = tid & 31;
    if (lane == 0) { sm[w] = s; sm[4 + w] = ss; }
    __syncthreads();
    float tot  = sm[0] + sm[1] + sm[2] + sm[3];
    float tot2 = sm[4] + sm[5] + sm[6] + sm[7];
    float mean = tot * (1.0f / Dm);
    float var  = tot2 * (1.0f / Dm) - mean * mean;
    float inv  = rsqrtf(var + 1e-5f);
    float4 g4 = ((const float4*)gamma)[tid];
    float4 b4 = ((const float4*)beta)[tid];
    float4 o;
    o.x = round_tf32((v.x - mean) * inv * g4.x + b4.x);
    o.y = round_tf32((v.y - mean) * inv * g4.y + b4.y);
    o.z = round_tf32((v.z - mean) * inv * g4.z + b4.z);
    o.w = round_tf32((v.w - mean) * inv * g4.w + b4.w);
    ((float4*)(out + (size_t)row * Dm))[tid] = o;
}

// ---------------- TF32 GEMM v2: BK=32, 3-stage, dynamic smem -------------
// smem per stage: A 128x32 w (16KB) + B 128x32 w (16KB). 3 stages = 96KB.
// layout: phys(row,k16B) = row*128B + ((k16B ^ (row&7))*16B)
#define GSTG_B  16384                 // bytes per A (or B) stage
#define GBOFF   49152                 // B region byte offset
#define GSMEM_B 98304

__device__ __forceinline__ float gelu_exact(float x) {
    return 0.5f * x * (1.0f + erff(x * 0.70710678118654752f));
}

template<int N, int K, bool BIAS, bool GELU, bool RES, bool ROUND>
__global__ __launch_bounds__(256, 2) void tgemm(
    const float* __restrict__ A, const float* __restrict__ WT,
    const float* __restrict__ bias, const float* __restrict__ res,
    float* __restrict__ C)
{
    extern __shared__ uint32_t gsm[];
    uint32_t smb = smem_u32(gsm);

    int tid = threadIdx.x, lane = tid & 31, warp = tid >> 5;
    int brow = blockIdx.y * 128, bcol = blockIdx.x * 128;
    int wm = (warp >> 1) * 32, wn = (warp & 1) * 64;
    int la = lane & 7, grp = lane >> 3, g = lane >> 2, t = lane & 3;

    // staging: thread -> (row r0 + 32*i, 16B col kc), i = 0..3
    int r0 = tid >> 3, kc = tid & 7;
    const float* Ag = A  + (size_t)(brow + r0) * K + kc * 4;
    const float* Bg = WT + (size_t)(bcol + r0) * K + kc * 4;
    uint32_t dA = smb + (uint32_t)(r0 * 128 + ((kc ^ (r0 & 7)) << 4));
    uint32_t dB = dA + GBOFF;

    // ldsm addresses
    uint32_t aAddr[2];
    #pragma unroll
    for (int mi = 0; mi < 2; mi++) {
        int r = wm + mi * 16 + la + (grp & 1) * 8;
        int c = grp >> 1;
        aAddr[mi] = smb + (uint32_t)(r * 128 + ((c ^ (r & 7)) << 4));
    }
    uint32_t bAddr;
    {
        int n = wn + (lane & 7) + ((lane >> 4) & 1) * 8;
        int c = (lane >> 3) & 1;
        bAddr = smb + GBOFF + (uint32_t)(n * 128 + ((c ^ (n & 7)) << 4));
    }

    float acc[2][8][4];
    #pragma unroll
    for (int mi = 0; mi < 2; mi++)
        #pragma unroll
        for (int ni = 0; ni < 8; ni++)
            #pragma unroll
            for (int c = 0; c < 4; c++) acc[mi][ni][c] = 0.0f;

    constexpr int iters = K / 32;

    // prologue: prefetch stages 0,1
    #pragma unroll
    for (int p = 0; p < 2; p++) {
        uint32_t oa = dA + p * GSTG_B, ob = dB + p * GSTG_B;
        const float* a = Ag + p * 32;
        const float* w = Bg + p * 32;
        #pragma unroll
        for (int i = 0; i < 4; i++) {
            cpa16(oa + i * 4096, a + (size_t)i * 32 * K);
            cpa16(ob + i * 4096, w + (size_t)i * 32 * K);
        }
        CP_COMMIT();
    }

    #pragma unroll 1
    for (int it = 0; it < iters; ++it) {
        CP_WAIT1();
        __syncthreads();
        if (it + 2 < iters) {
            uint32_t so = (uint32_t)(((it + 2) % 3) * GSTG_B);
            const float* a = Ag + (it + 2) * 32;
            const float* w = Bg + (it + 2) * 32;
            #pragma unroll
            for (int i = 0; i < 4; i++) {
                cpa16(dA + so + i * 4096, a + (size_t)i * 32 * K);
                cpa16(dB + so + i * 4096, w + (size_t)i * 32 * K);
            }
        }
        CP_COMMIT();

        uint32_t so = (uint32_t)((it % 3) * GSTG_B);
        #pragma unroll
        for (int ks = 0; ks < 4; ks++) {
            uint32_t kx = (uint32_t)(ks << 5);
            uint32_t af0[4], af1[4];
            ldsm4(af0, (aAddr[0] + so) ^ kx);
            ldsm4(af1, (aAddr[1] + so) ^ kx);
            #pragma unroll
            for (int ng = 0; ng < 4; ng++) {
                uint32_t bf[4];
                ldsm4(bf, (bAddr + so + ng * 2048) ^ kx);
                mma8(acc[0][ng * 2],     af0, bf[0], bf[1]);
                mma8(acc[0][ng * 2 + 1], af0, bf[2], bf[3]);
                mma8(acc[1][ng * 2],     af1, bf[0], bf[1]);
                mma8(acc[1][ng * 2 + 1], af1, bf[2], bf[3]);
            }
        }
    }

    // epilogue
    #pragma unroll
    for (int mi = 0; mi < 2; mi++) {
        int r0e = brow + wm + mi * 16 + g;
        #pragma unroll
        for (int ni = 0; ni < 8; ni++) {
            int col = bcol + wn + ni * 8 + t * 2;
            float2 v0 = {acc[mi][ni][0], acc[mi][ni][1]};
            float2 v1 = {acc[mi][ni][2], acc[mi][ni][3]};
            if (BIAS) {
                float2 bb = *(const float2*)&bias[col];
                v0.x += bb.x; v0.y += bb.y; v1.x += bb.x; v1.y += bb.y;
            }
            if (GELU) {
                v0.x = gelu_exact(v0.x); v0.y = gelu_exact(v0.y);
                v1.x = gelu_exact(v1.x); v1.y = gelu_exact(v1.y);
            }
            if (RES) {
                float2 q0 = *(const float2*)&res[(size_t)r0e * N + col];
                float2 q1 = *(const float2*)&res[(size_t)(r0e + 8) * N + col];
                v0.x += q0.x; v0.y += q0.y; v1.x += q1.x; v1.y += q1.y;
            }
            if (ROUND) {
                v0.x = round_tf32(v0.x); v0.y = round_tf32(v0.y);
                v1.x = round_tf32(v1.x); v1.y = round_tf32(v1.y);
            }
            *(float2*)&C[(size_t)r0e * N + col] = v0;
            *(float2*)&C[(size_t)(r0e + 8) * N + col] = v1;
        }
    }
}

// ---------------- TF32 flash attention (unchanged from R6) ----------------
#define KPW      68
#define OFF_QP   0
#define OFF_K    8704
#define OFF_V    17408
#define OFF_EK   26112
#define ATT_WORDS 26240
#define ATT_BYTES (ATT_WORDS * 4)
#define KVSTG    4352

__device__ __forceinline__ float bias_f(float eq, float ek, float alpha) {
    float diff = (ek - eq) * 1e-3f;
    float b = -alpha * fmaxf(diff, 0.0f);
    return fminf(fmaxf(b, -10.0f), 0.0f);
}

__global__ __launch_bounds__(256, 2) void attn_tc(
    const float* __restrict__ qkv, const float* __restrict__ vT,
    const float* __restrict__ elev, const float* __restrict__ alpha_p,
    float* __restrict__ out)
{
    extern __shared__ uint32_t dsm[];
    uint32_t smb = smem_u32(dsm);
    float* sEK = (float*)(dsm + OFF_EK);

    int bh = blockIdx.y;
    int b = bh >> 3, h = bh & 7;
    int q0 = blockIdx.x * 128;
    int tid = threadIdx.x, lane = tid & 31, warp = tid >> 5;
    int la = lane & 7, grp = lane >> 3, g = lane >> 2, t = lane & 3;
    float alpha = alpha_p[0];
    const float* eb = elev + b * Nseq;
    const float* qbase = qkv + ((size_t)(b * Nseq + q0)) * (3 * Dm) + h * HDim;
    const float* kvb   = qkv + ((size_t)(b * Nseq)) * (3 * Dm) + Dm + h * HDim;
    const float* vtb   = vT + (size_t)(bh * HDim) * Nseq;

    #pragma unroll
    for (int i = 0; i < 8; i++) {
        int idx = tid + i * 256;
        int r = idx >> 4, c4 = (idx & 15) * 4;
        cpa16(smb + (uint32_t)(OFF_QP + r * KPW + c4) * 4u,
              qbase + (size_t)r * (3 * Dm) + c4);
    }
    #pragma unroll
    for (int i = 0; i < 4; i++) {
        int idx = tid + i * 256;
        int r = idx >> 4, c4 = (idx & 15) * 4;
        cpa16(smb + (uint32_t)(OFF_K + r * KPW + c4) * 4u,
              kvb + (size_t)r * (3 * Dm) + c4);
        cpa16(smb + (uint32_t)(OFF_V + r * KPW + c4) * 4u,
              vtb + (size_t)r * Nseq + c4);
    }
    if (tid < 64) sEK[tid] = eb[tid];
    CP_COMMIT();
    CP_WAIT0();
    __syncthreads();

    int qr0 = warp * 16;
    uint32_t aAddr = smb +
        (uint32_t)(OFF_QP + (qr0 + la + (grp & 1) * 8) * KPW + (grp >> 1) * 4) * 4u;
    uint32_t qf[8][4];
    #pragma unroll
    for (int kc = 0; kc < 8; kc++) ldsm4(qf[kc], aAddr + kc * 32);

    float eq0 = eb[q0 + qr0 + g];
    float eq1 = eb[q0 + qr0 + g + 8];

    uint32_t bAddrK[4], bAddrV[4];
    #pragma unroll
    for (int nt = 0; nt < 4; nt++) {
        int r = nt * 16 + la + (grp >> 1) * 8;
        bAddrK[nt] = smb + (uint32_t)(OFF_K + r * KPW + (grp & 1) * 4) * 4u;
        bAddrV[nt] = smb + (uint32_t)(OFF_V + r * KPW + (grp & 1) * 4) * 4u;
    }

    float O[8][4];
    #pragma unroll
    for (int e = 0; e < 8; e++)
        O[e][0] = O[e][1] = O[e][2] = O[e][3] = 0.0f;
    float mi0 = -1e30f, mi1 = -1e30f, li0 = 0.0f, li1 = 0.0f;

    #pragma unroll 1
    for (int tt = 0; tt < Nseq / 64; tt++) {
        if (tt) { CP_WAIT0(); __syncthreads(); }
        if (tt + 1 < Nseq / 64) {
            int bufn = (tt + 1) & 1;
            int k0n = (tt + 1) * 64;
            const float* kb = kvb + (size_t)k0n * (3 * Dm);
            #pragma unroll
            for (int i = 0; i < 4; i++) {
                int idx = tid + i * 256;
                int r = idx >> 4, c4 = (idx & 15) * 4;
                cpa16(smb + (uint32_t)(OFF_K + bufn * KVSTG + r * KPW + c4) * 4u,
                      kb + (size_t)r * (3 * Dm) + c4);
                cpa16(smb + (uint32_t)(OFF_V + bufn * KVSTG + r * KPW + c4) * 4u,
                      vtb + (size_t)r * Nseq + k0n + c4);
            }
            if (tid < 64) sEK[bufn * 64 + tid] = eb[k0n + tid];
        }
        CP_COMMIT();

        int buf = tt & 1;
        uint32_t bOff = (uint32_t)(buf * KVSTG) * 4u;

        float S[8][4];
        #pragma unroll
        for (int nt = 0; nt < 8; nt++)
            S[nt][0] = S[nt][1] = S[nt][2] = S[nt][3] = 0.0f;
        #pragma unroll
        for (int kc = 0; kc < 8; kc++) {
            #pragma unroll
            for (int nt4 = 0; nt4 < 4; nt4++) {
                uint32_t bf[4];
                ldsm4(bf, bAddrK[nt4] + bOff + kc * 32);
                mma8(S[nt4 * 2], qf[kc], bf[0], bf[1]);
                mma8(S[nt4 * 2 + 1], qf[kc], bf[2], bf[3]);
            }
        }

        float rm0 = -1e30f, rm1 = -1e30f;
        #pragma unroll
        for (int nt = 0; nt < 8; nt++) {
            float ek0 = sEK[buf * 64 + nt * 8 + t * 2];
            float ek1 = sEK[buf * 64 + nt * 8 + t * 2 + 1];
            S[nt][0] = S[nt][0] * SCALE + bias_f(eq0, ek0, alpha);
            S[nt][1] = S[nt][1] * SCALE + bias_f(eq0, ek1, alpha);
            S[nt][2] = S[nt][2] * SCALE + bias_f(eq1, ek0, alpha);
            S[nt][3] = S[nt][3] * SCALE + bias_f(eq1, ek1, alpha);
            rm0 = fmaxf(rm0, fmaxf(S[nt][0], S[nt][1]));
            rm1 = fmaxf(rm1, fmaxf(S[nt][2], S[nt][3]));
        }
        rm0 = fmaxf(rm0, __shfl_xor_sync(0xffffffffu, rm0, 1));
        rm0 = fmaxf(rm0, __shfl_xor_sync(0xffffffffu, rm0, 2));
        rm1 = fmaxf(rm1, __shfl_xor_sync(0xffffffffu, rm1, 1));
        rm1 = fmaxf(rm1, __shfl_xor_sync(0xffffffffu, rm1, 2));
        float mn0 = fmaxf(mi0, rm0), mn1 = fmaxf(mi1, rm1);
        float c0 = __expf(mi0 - mn0), c1 = __expf(mi1 - mn1);
        mi0 = mn0; mi1 = mn1;
        float rs0 = 0.0f, rs1 = 0.0f;
        #pragma unroll
        for (int nt = 0; nt < 8; nt++) {
            S[nt][0] = __expf(S[nt][0] - mn0); rs0 += S[nt][0];
            S[nt][1] = __expf(S[nt][1] - mn0); rs0 += S[nt][1];
            S[nt][2] = __expf(S[nt][2] - mn1); rs1 += S[nt][2];
            S[nt][3] = __expf(S[nt][3] - mn1); rs1 += S[nt][3];
        }
        rs0 += __shfl_xor_sync(0xffffffffu, rs0, 1);
        rs0 += __shfl_xor_sync(0xffffffffu, rs0, 2);
        rs1 += __shfl_xor_sync(0xffffffffu, rs1, 1);
        rs1 += __shfl_xor_sync(0xffffffffu, rs1, 2);
        li0 = li0 * c0 + rs0;
        li1 = li1 * c1 + rs1;
        #pragma unroll
        for (int e = 0; e < 8; e++) {
            O[e][0] *= c0; O[e][1] *= c0; O[e][2] *= c1; O[e][3] *= c1;
        }

        #pragma unroll
        for (int nt = 0; nt < 8; nt++) {
            uint32_t* p0 = &dsm[OFF_QP + (qr0 + g) * KPW + nt * 8 + t * 2];
            uint32_t* p1 = &dsm[OFF_QP + (qr0 + 8 + g) * KPW + nt * 8 + t * 2];
            p0[0] = cvt_tf32(S[nt][0]); p0[1] = cvt_tf32(S[nt][1]);
            p1[0] = cvt_tf32(S[nt][2]); p1[1] = cvt_tf32(S[nt][3]);
        }
        __syncwarp();

        #pragma unroll
        for (int kc = 0; kc < 8; kc++) {
            uint32_t pf[4];
            ldsm4(pf, aAddr + kc * 32);
            #pragma unroll
            for (int nt4 = 0; nt4 < 4; nt4++) {
                uint32_t bf[4];
                ldsm4(bf, bAddrV[nt4] + bOff + kc * 32);
                mma8(O[nt4 * 2],     pf, bf[0], bf[1]);
                mma8(O[nt4 * 2 + 1], pf, bf[2], bf[3]);
            }
        }
    }

    float inv0 = 1.0f / li0, inv1 = 1.0f / li1;
    int row0 = b * Nseq + q0 + qr0 + g;
    #pragma unroll
    for (int e = 0; e < 8; e++) {
        int col = h * HDim + e * 8 + t * 2;
        float2 o0 = {round_tf32(O[e][0] * inv0), round_tf32(O[e][1] * inv0)};
        float2 o1 = {round_tf32(O[e][2] * inv1), round_tf32(O[e][3] * inv1)};
        *(float2*)&out[(size_t)row0 * Dm + col] = o0;
        *(float2*)&out[(size_t)(row0 + 8) * Dm + col] = o1;
    }
}

// ---------------- launch ----------------
extern "C" void kernel_launch(void* const* d_in, const int* in_sizes, int n_in,
                              void* d_out, int out_size)
{
    const float* x     = (const float*)d_in[0];
    const float* elev  = (const float*)d_in[1];
    const float* ln1g  = (const float*)d_in[2];
    const float* ln1b  = (const float*)d_in[3];
    const float* qkvw  = (const float*)d_in[4];
    const float* alpha = (const float*)d_in[5];
    const float* projw = (const float*)d_in[6];
    const float* projb = (const float*)d_in[7];
    const float* ln2g  = (const float*)d_in[8];
    const float* ln2b  = (const float*)d_in[9];
    const float* fc1w  = (const float*)d_in[10];
    const float* fc1b  = (const float*)d_in[11];
    const float* fc2w  = (const float*)d_in[12];
    const float* fc2b  = (const float*)d_in[13];
    float* out = (float*)d_out;

    float *ph, *pqkv, *pattn, *px1, *pact, *pwt, *pvt;
    cudaGetSymbolAddress((void**)&ph,    g_h);
    cudaGetSymbolAddress((void**)&pqkv,  g_qkv);
    cudaGetSymbolAddress((void**)&pattn, g_attn);
    cudaGetSymbolAddress((void**)&px1,   g_x1);
    cudaGetSymbolAddress((void**)&pact,  g_act);
    cudaGetSymbolAddress((void**)&pwt,   g_wt);
    cudaGetSymbolAddress((void**)&pvt,   g_vT);

    cudaFuncSetAttribute(attn_tc,
        cudaFuncAttributeMaxDynamicSharedMemorySize, ATT_BYTES);
    cudaFuncSetAttribute(tgemm<1536, 512, false, false, false, true>,
        cudaFuncAttributeMaxDynamicSharedMemorySize, GSMEM_B);
    cudaFuncSetAttribute(tgemm<512, 512, true, false, true, false>,
        cudaFuncAttributeMaxDynamicSharedMemorySize, GSMEM_B);
    cudaFuncSetAttribute(tgemm<2048, 512, true, true, false, true>,
        cudaFuncAttributeMaxDynamicSharedMemorySize, GSMEM_B);
    cudaFuncSetAttribute(tgemm<512, 2048, true, false, true, false>,
        cudaFuncAttributeMaxDynamicSharedMemorySize, GSMEM_B);

    // 0. weight transpose + tf32 round
    transpose_cvt<<<dim3(48, 16), dim3(32, 8)>>>(qkvw,  pwt + WT_QKV,  Dm,   3 * Dm);
    transpose_cvt<<<dim3(16, 16), dim3(32, 8)>>>(projw, pwt + WT_PROJ, Dm,   Dm);
    transpose_cvt<<<dim3(64, 16), dim3(32, 8)>>>(fc1w,  pwt + WT_FC1,  Dm,   MLPH);
    transpose_cvt<<<dim3(16, 64), dim3(32, 8)>>>(fc2w,  pwt + WT_FC2,  MLPH, Dm);

    // 1. LN1
    ln_kernel<<<ROWS, 128>>>(x, ln1g, ln1b, ph);
    // 2. qkv (ROUND=true)
    tgemm<1536, 512, false, false, false, true><<<dim3(12, 64), 256, GSMEM_B>>>(
        ph, pwt + WT_QKV, nullptr, nullptr, pqkv);
    // 2b. V transpose
    vtrans_kernel<<<dim3(64, 2, 32), dim3(32, 8)>>>(pqkv, pvt);
    // 3. attention
    attn_tc<<<dim3(Nseq / 128, Bsz * Hh), 256, ATT_BYTES>>>(
        pqkv, pvt, elev, alpha, pattn);
    // 4. x1 = x + attn @ proj_w + proj_b
    tgemm<512, 512, true, false, true, false><<<dim3(4, 64), 256, GSMEM_B>>>(
        pattn, pwt + WT_PROJ, projb, x, px1);
    // 5. LN2
    ln_kernel<<<ROWS, 128>>>(px1, ln2g, ln2b, ph);
    // 6. act = gelu(h2 @ fc1_w + fc1_b)
    tgemm<2048, 512, true, true, false, true><<<dim3(16, 64), 256, GSMEM_B>>>(
        ph, pwt + WT_FC1, fc1b, nullptr, pact);
    // 7. out = x1 + act @ fc2_w + fc2_b
    tgemm<512, 2048, true, false, true, false><<<dim3(4, 64), 256, GSMEM_B>>>(
        pact, pwt + WT_FC2, fc2b, px1, out);
}

// round 9
// speedup vs baseline: 1.1980x; 1.0248x over previous
#include <cuda_runtime.h>
#include <math.h>
#include <stdint.h>

#define Bsz   4
#define Nseq  2048
#define Dm    512
#define Hh    8
#define HDim  64
#define MLPH  2048
#define ROWS  (Bsz * Nseq)
#define SCALE 0.125f

// ---------------- scratch ----------------
__device__ float g_h[ROWS * Dm];
__device__ float g_qkv[ROWS * 3 * Dm];
__device__ float g_attn[ROWS * Dm];
__device__ float g_x1[ROWS * Dm];
__device__ float g_act[ROWS * MLPH];
__device__ float g_wt[3145728];
__device__ float g_vT[Bsz * Hh * HDim * Nseq];
#define WT_QKV  0
#define WT_PROJ 786432
#define WT_FC1  1048576
#define WT_FC2  2097152

// ---------------- helpers ----------------
__device__ __forceinline__ uint32_t cvt_tf32(float x) {
    uint32_t r; asm("cvt.rna.tf32.f32 %0, %1;" : "=r"(r) : "f"(x)); return r;
}
__device__ __forceinline__ float round_tf32(float x) {
    return __uint_as_float(cvt_tf32(x));
}
__device__ __forceinline__ uint32_t smem_u32(const void* p) {
    return (uint32_t)__cvta_generic_to_shared(p);
}
__device__ __forceinline__ void ldsm4(uint32_t r[4], uint32_t a) {
    asm volatile("ldmatrix.sync.aligned.m8n8.x4.shared.b16 {%0,%1,%2,%3}, [%4];"
        : "=r"(r[0]), "=r"(r[1]), "=r"(r[2]), "=r"(r[3]) : "r"(a));
}
__device__ __forceinline__ void mma8(float d[4], const uint32_t a[4],
                                     uint32_t b0, uint32_t b1) {
    asm volatile(
        "mma.sync.aligned.m16n8k8.row.col.f32.tf32.tf32.f32 "
        "{%0,%1,%2,%3}, {%4,%5,%6,%7}, {%8,%9}, {%0,%1,%2,%3};"
        : "+f"(d[0]), "+f"(d[1]), "+f"(d[2]), "+f"(d[3])
        : "r"(a[0]), "r"(a[1]), "r"(a[2]), "r"(a[3]), "r"(b0), "r"(b1));
}
__device__ __forceinline__ void cpa16(uint32_t dst, const void* src) {
    asm volatile("cp.async.cg.shared.global [%0], [%1], 16;\n"
        :: "r"(dst), "l"(src));
}
#define CP_COMMIT() asm volatile("cp.async.commit_group;\n" ::: "memory")
#define CP_WAIT1()  asm volatile("cp.async.wait_group 1;\n" ::: "memory")
#define CP_WAIT0()  asm volatile("cp.async.wait_group 0;\n" ::: "memory")

// ---------------- weight transpose + tf32 round ----------------
__global__ __launch_bounds__(256) void transpose_cvt(
    const float* __restrict__ in, float* __restrict__ out, int K, int N)
{
    __shared__ float t[32][33];
    int n0 = blockIdx.x * 32, k0 = blockIdx.y * 32;
    int tx = threadIdx.x, ty = threadIdx.y;
    #pragma unroll
    for (int j = 0; j < 32; j += 8)
        t[ty + j][tx] = in[(size_t)(k0 + ty + j) * N + n0 + tx];
    __syncthreads();
    #pragma unroll
    for (int j = 0; j < 32; j += 8)
        out[(size_t)(n0 + ty + j) * K + k0 + tx] = round_tf32(t[tx][ty + j]);
}

// ---------------- V transpose ----------------
__global__ __launch_bounds__(256) void vtrans_kernel(
    const float* __restrict__ qkv, float* __restrict__ vT)
{
    __shared__ float t[32][33];
    int bh = blockIdx.z;
    int b = bh >> 3, h = bh & 7;
    int n0 = blockIdx.x * 32, e0 = blockIdx.y * 32;
    int tx = threadIdx.x, ty = threadIdx.y;
    const float* src = qkv + (size_t)(b * Nseq) * (3 * Dm) + 2 * Dm + h * HDim;
    #pragma unroll
    for (int j = 0; j < 32; j += 8)
        t[ty + j][tx] = src[(size_t)(n0 + ty + j) * (3 * Dm) + e0 + tx];
    __syncthreads();
    #pragma unroll
    for (int j = 0; j < 32; j += 8)
        vT[(size_t)(bh * HDim + e0 + ty + j) * Nseq + n0 + tx] = t[tx][ty + j];
}

// ---------------- LayerNorm ----------------
__global__ __launch_bounds__(128) void ln_kernel(
    const float* __restrict__ in, const float* __restrict__ gamma,
    const float* __restrict__ beta, float* __restrict__ out)
{
    int row = blockIdx.x;
    int tid = threadIdx.x;
    const float4* p = (const float4*)(in + (size_t)row * Dm);
    float4 v = p[tid];
    float s  = v.x + v.y + v.z + v.w;
    float ss = v.x * v.x + v.y * v.y + v.z * v.z + v.w * v.w;
    #pragma unroll
    for (int o = 16; o; o >>= 1) {
        s  += __shfl_xor_sync(0xffffffffu, s,  o);
        ss += __shfl_xor_sync(0xffffffffu, ss, o);
    }
    __shared__ float sm[8];
    int w = tid >> 5, lane = tid & 31;
    if (lane == 0) { sm[w] = s; sm[4 + w] = ss; }
    __syncthreads();
    float tot  = sm[0] + sm[1] + sm[2] + sm[3];
    float tot2 = sm[4] + sm[5] + sm[6] + sm[7];
    float mean = tot * (1.0f / Dm);
    float var  = tot2 * (1.0f / Dm) - mean * mean;
    float inv  = rsqrtf(var + 1e-5f);
    float4 g4 = ((const float4*)gamma)[tid];
    float4 b4 = ((const float4*)beta)[tid];
    float4 o;
    o.x = round_tf32((v.x - mean) * inv * g4.x + b4.x);
    o.y = round_tf32((v.y - mean) * inv * g4.y + b4.y);
    o.z = round_tf32((v.z - mean) * inv * g4.z + b4.z);
    o.w = round_tf32((v.w - mean) * inv * g4.w + b4.w);
    ((float4*)(out + (size_t)row * Dm))[tid] = o;
}

// ---------------- TF32 GEMM v3: 64x64 warp tiles, 128 thr ----------------
// block 128x128, 4 warps (2x2), BK=32, 3-stage cp.async, SW128 atom swizzle.
#define GSTG_B  16384
#define GBOFF   49152
#define GSMEM_B 98304

__device__ __forceinline__ float gelu_exact(float x) {
    return 0.5f * x * (1.0f + erff(x * 0.70710678118654752f));
}

template<int N, int K, bool BIAS, bool GELU, bool RES, bool ROUND>
__global__ __launch_bounds__(128, 2) void tgemm(
    const float* __restrict__ A, const float* __restrict__ WT,
    const float* __restrict__ bias, const float* __restrict__ res,
    float* __restrict__ C)
{
    extern __shared__ uint32_t gsm[];
    uint32_t smb = smem_u32(gsm);

    int tid = threadIdx.x, lane = tid & 31, warp = tid >> 5;
    int brow = blockIdx.y * 128, bcol = blockIdx.x * 128;
    int wm = (warp >> 1) * 64, wn = (warp & 1) * 64;
    int la = lane & 7, grp = lane >> 3, g = lane >> 2, t = lane & 3;

    // staging: thread -> (row r0 + 16*i, 16B chunk kc), i = 0..7
    int r0 = tid >> 3, kc = tid & 7;
    const float* Ag = A  + (size_t)(brow + r0) * K + kc * 4;
    const float* Bg = WT + (size_t)(bcol + r0) * K + kc * 4;
    uint32_t dA = smb + (uint32_t)(r0 * 128 + ((kc ^ (r0 & 7)) << 4));
    uint32_t dB = dA + GBOFF;

    // ldsm addresses: 4 A m-tiles, 4 B n-tiles
    uint32_t aAddr[4];
    #pragma unroll
    for (int mi = 0; mi < 4; mi++) {
        int r = wm + mi * 16 + la + (grp & 1) * 8;
        int c = grp >> 1;
        aAddr[mi] = smb + (uint32_t)(r * 128 + ((c ^ (r & 7)) << 4));
    }
    uint32_t bAddr[4];
    #pragma unroll
    for (int nt = 0; nt < 4; nt++) {
        int n = wn + nt * 16 + (lane & 7) + ((lane >> 4) & 1) * 8;
        int c = (lane >> 3) & 1;
        bAddr[nt] = smb + GBOFF + (uint32_t)(n * 128 + ((c ^ (n & 7)) << 4));
    }

    float acc[4][8][4];
    #pragma unroll
    for (int mi = 0; mi < 4; mi++)
        #pragma unroll
        for (int ni = 0; ni < 8; ni++)
            #pragma unroll
            for (int c = 0; c < 4; c++) acc[mi][ni][c] = 0.0f;

    constexpr int iters = K / 32;

    // prologue: prefetch stages 0,1
    #pragma unroll
    for (int p = 0; p < 2; p++) {
        uint32_t oa = dA + p * GSTG_B, ob = dB + p * GSTG_B;
        const float* a = Ag + p * 32;
        const float* w = Bg + p * 32;
        #pragma unroll
        for (int i = 0; i < 8; i++) {
            cpa16(oa + i * 2048, a + (size_t)i * 16 * K);
            cpa16(ob + i * 2048, w + (size_t)i * 16 * K);
        }
        CP_COMMIT();
    }

    #pragma unroll 1
    for (int it = 0; it < iters; ++it) {
        CP_WAIT1();
        __syncthreads();
        if (it + 2 < iters) {
            uint32_t so = (uint32_t)(((it + 2) % 3) * GSTG_B);
            const float* a = Ag + (it + 2) * 32;
            const float* w = Bg + (it + 2) * 32;
            #pragma unroll
            for (int i = 0; i < 8; i++) {
                cpa16(dA + so + i * 2048, a + (size_t)i * 16 * K);
                cpa16(dB + so + i * 2048, w + (size_t)i * 16 * K);
            }
        }
        CP_COMMIT();

        uint32_t so = (uint32_t)((it % 3) * GSTG_B);
        #pragma unroll
        for (int ks = 0; ks < 4; ks++) {
            uint32_t kx = (uint32_t)(ks << 5);
            uint32_t af[4][4];
            #pragma unroll
            for (int mi = 0; mi < 4; mi++)
                ldsm4(af[mi], (aAddr[mi] + so) ^ kx);
            #pragma unroll
            for (int nt = 0; nt < 4; nt++) {
                uint32_t bf[4];
                ldsm4(bf, (bAddr[nt] + so) ^ kx);
                #pragma unroll
                for (int mi = 0; mi < 4; mi++) {
                    mma8(acc[mi][nt * 2],     af[mi], bf[0], bf[1]);
                    mma8(acc[mi][nt * 2 + 1], af[mi], bf[2], bf[3]);
                }
            }
        }
    }

    // epilogue
    #pragma unroll
    for (int mi = 0; mi < 4; mi++) {
        int r0e = brow + wm + mi * 16 + g;
        #pragma unroll
        for (int ni = 0; ni < 8; ni++) {
            int col = bcol + wn + ni * 8 + t * 2;
            float2 v0 = {acc[mi][ni][0], acc[mi][ni][1]};
            float2 v1 = {acc[mi][ni][2], acc[mi][ni][3]};
            if (BIAS) {
                float2 bb = *(const float2*)&bias[col];
                v0.x += bb.x; v0.y += bb.y; v1.x += bb.x; v1.y += bb.y;
            }
            if (GELU) {
                v0.x = gelu_exact(v0.x); v0.y = gelu_exact(v0.y);
                v1.x = gelu_exact(v1.x); v1.y = gelu_exact(v1.y);
            }
            if (RES) {
                float2 q0 = *(const float2*)&res[(size_t)r0e * N + col];
                float2 q1 = *(const float2*)&res[(size_t)(r0e + 8) * N + col];
                v0.x += q0.x; v0.y += q0.y; v1.x += q1.x; v1.y += q1.y;
            }
            if (ROUND) {
                v0.x = round_tf32(v0.x); v0.y = round_tf32(v0.y);
                v1.x = round_tf32(v1.x); v1.y = round_tf32(v1.y);
            }
            *(float2*)&C[(size_t)r0e * N + col] = v0;
            *(float2*)&C[(size_t)(r0e + 8) * N + col] = v1;
        }
    }
}

// ---------------- TF32 flash attention (unchanged) ----------------
#define KPW      68
#define OFF_QP   0
#define OFF_K    8704
#define OFF_V    17408
#define OFF_EK   26112
#define ATT_WORDS 26240
#define ATT_BYTES (ATT_WORDS * 4)
#define KVSTG    4352

__device__ __forceinline__ float bias_f(float eq, float ek, float alpha) {
    float diff = (ek - eq) * 1e-3f;
    float b = -alpha * fmaxf(diff, 0.0f);
    return fminf(fmaxf(b, -10.0f), 0.0f);
}

__global__ __launch_bounds__(256, 2) void attn_tc(
    const float* __restrict__ qkv, const float* __restrict__ vT,
    const float* __restrict__ elev, const float* __restrict__ alpha_p,
    float* __restrict__ out)
{
    extern __shared__ uint32_t dsm[];
    uint32_t smb = smem_u32(dsm);
    float* sEK = (float*)(dsm + OFF_EK);

    int bh = blockIdx.y;
    int b = bh >> 3, h = bh & 7;
    int q0 = blockIdx.x * 128;
    int tid = threadIdx.x, lane = tid & 31, warp = tid >> 5;
    int la = lane & 7, grp = lane >> 3, g = lane >> 2, t = lane & 3;
    float alpha = alpha_p[0];
    const float* eb = elev + b * Nseq;
    const float* qbase = qkv + ((size_t)(b * Nseq + q0)) * (3 * Dm) + h * HDim;
    const float* kvb   = qkv + ((size_t)(b * Nseq)) * (3 * Dm) + Dm + h * HDim;
    const float* vtb   = vT + (size_t)(bh * HDim) * Nseq;

    #pragma unroll
    for (int i = 0; i < 8; i++) {
        int idx = tid + i * 256;
        int r = idx >> 4, c4 = (idx & 15) * 4;
        cpa16(smb + (uint32_t)(OFF_QP + r * KPW + c4) * 4u,
              qbase + (size_t)r * (3 * Dm) + c4);
    }
    #pragma unroll
    for (int i = 0; i < 4; i++) {
        int idx = tid + i * 256;
        int r = idx >> 4, c4 = (idx & 15) * 4;
        cpa16(smb + (uint32_t)(OFF_K + r * KPW + c4) * 4u,
              kvb + (size_t)r * (3 * Dm) + c4);
        cpa16(smb + (uint32_t)(OFF_V + r * KPW + c4) * 4u,
              vtb + (size_t)r * Nseq + c4);
    }
    if (tid < 64) sEK[tid] = eb[tid];
    CP_COMMIT();
    CP_WAIT0();
    __syncthreads();

    int qr0 = warp * 16;
    uint32_t aAddr = smb +
        (uint32_t)(OFF_QP + (qr0 + la + (grp & 1) * 8) * KPW + (grp >> 1) * 4) * 4u;
    uint32_t qf[8][4];
    #pragma unroll
    for (int kc = 0; kc < 8; kc++) ldsm4(qf[kc], aAddr + kc * 32);

    float eq0 = eb[q0 + qr0 + g];
    float eq1 = eb[q0 + qr0 + g + 8];

    uint32_t bAddrK[4], bAddrV[4];
    #pragma unroll
    for (int nt = 0; nt < 4; nt++) {
        int r = nt * 16 + la + (grp >> 1) * 8;
        bAddrK[nt] = smb + (uint32_t)(OFF_K + r * KPW + (grp & 1) * 4) * 4u;
        bAddrV[nt] = smb + (uint32_t)(OFF_V + r * KPW + (grp & 1) * 4) * 4u;
    }

    float O[8][4];
    #pragma unroll
    for (int e = 0; e < 8; e++)
        O[e][0] = O[e][1] = O[e][2] = O[e][3] = 0.0f;
    float mi0 = -1e30f, mi1 = -1e30f, li0 = 0.0f, li1 = 0.0f;

    #pragma unroll 1
    for (int tt = 0; tt < Nseq / 64; tt++) {
        if (tt) { CP_WAIT0(); __syncthreads(); }
        if (tt + 1 < Nseq / 64) {
            int bufn = (tt + 1) & 1;
            int k0n = (tt + 1) * 64;
            const float* kb = kvb + (size_t)k0n * (3 * Dm);
            #pragma unroll
            for (int i = 0; i < 4; i++) {
                int idx = tid + i * 256;
                int r = idx >> 4, c4 = (idx & 15) * 4;
                cpa16(smb + (uint32_t)(OFF_K + bufn * KVSTG + r * KPW + c4) * 4u,
                      kb + (size_t)r * (3 * Dm) + c4);
                cpa16(smb + (uint32_t)(OFF_V + bufn * KVSTG + r * KPW + c4) * 4u,
                      vtb + (size_t)r * Nseq + k0n + c4);
            }
            if (tid < 64) sEK[bufn * 64 + tid] = eb[k0n + tid];
        }
        CP_COMMIT();

        int buf = tt & 1;
        uint32_t bOff = (uint32_t)(buf * KVSTG) * 4u;

        float S[8][4];
        #pragma unroll
        for (int nt = 0; nt < 8; nt++)
            S[nt][0] = S[nt][1] = S[nt][2] = S[nt][3] = 0.0f;
        #pragma unroll
        for (int kc = 0; kc < 8; kc++) {
            #pragma unroll
            for (int nt4 = 0; nt4 < 4; nt4++) {
                uint32_t bf[4];
                ldsm4(bf, bAddrK[nt4] + bOff + kc * 32);
                mma8(S[nt4 * 2], qf[kc], bf[0], bf[1]);
                mma8(S[nt4 * 2 + 1], qf[kc], bf[2], bf[3]);
            }
        }

        float rm0 = -1e30f, rm1 = -1e30f;
        #pragma unroll
        for (int nt = 0; nt < 8; nt++) {
            float ek0 = sEK[buf * 64 + nt * 8 + t * 2];
            float ek1 = sEK[buf * 64 + nt * 8 + t * 2 + 1];
            S[nt][0] = S[nt][0] * SCALE + bias_f(eq0, ek0, alpha);
            S[nt][1] = S[nt][1] * SCALE + bias_f(eq0, ek1, alpha);
            S[nt][2] = S[nt][2] * SCALE + bias_f(eq1, ek0, alpha);
            S[nt][3] = S[nt][3] * SCALE + bias_f(eq1, ek1, alpha);
            rm0 = fmaxf(rm0, fmaxf(S[nt][0], S[nt][1]));
            rm1 = fmaxf(rm1, fmaxf(S[nt][2], S[nt][3]));
        }
        rm0 = fmaxf(rm0, __shfl_xor_sync(0xffffffffu, rm0, 1));
        rm0 = fmaxf(rm0, __shfl_xor_sync(0xffffffffu, rm0, 2));
        rm1 = fmaxf(rm1, __shfl_xor_sync(0xffffffffu, rm1, 1));
        rm1 = fmaxf(rm1, __shfl_xor_sync(0xffffffffu, rm1, 2));
        float mn0 = fmaxf(mi0, rm0), mn1 = fmaxf(mi1, rm1);
        float c0 = __expf(mi0 - mn0), c1 = __expf(mi1 - mn1);
        mi0 = mn0; mi1 = mn1;
        float rs0 = 0.0f, rs1 = 0.0f;
        #pragma unroll
        for (int nt = 0; nt < 8; nt++) {
            S[nt][0] = __expf(S[nt][0] - mn0); rs0 += S[nt][0];
            S[nt][1] = __expf(S[nt][1] - mn0); rs0 += S[nt][1];
            S[nt][2] = __expf(S[nt][2] - mn1); rs1 += S[nt][2];
            S[nt][3] = __expf(S[nt][3] - mn1); rs1 += S[nt][3];
        }
        rs0 += __shfl_xor_sync(0xffffffffu, rs0, 1);
        rs0 += __shfl_xor_sync(0xffffffffu, rs0, 2);
        rs1 += __shfl_xor_sync(0xffffffffu, rs1, 1);
        rs1 += __shfl_xor_sync(0xffffffffu, rs1, 2);
        li0 = li0 * c0 + rs0;
        li1 = li1 * c1 + rs1;
        #pragma unroll
        for (int e = 0; e < 8; e++) {
            O[e][0] *= c0; O[e][1] *= c0; O[e][2] *= c1; O[e][3] *= c1;
        }

        #pragma unroll
        for (int nt = 0; nt < 8; nt++) {
            uint32_t* p0 = &dsm[OFF_QP + (qr0 + g) * KPW + nt * 8 + t * 2];
            uint32_t* p1 = &dsm[OFF_QP + (qr0 + 8 + g) * KPW + nt * 8 + t * 2];
            p0[0] = cvt_tf32(S[nt][0]); p0[1] = cvt_tf32(S[nt][1]);
            p1[0] = cvt_tf32(S[nt][2]); p1[1] = cvt_tf32(S[nt][3]);
        }
        __syncwarp();

        #pragma unroll
        for (int kc = 0; kc < 8; kc++) {
            uint32_t pf[4];
            ldsm4(pf, aAddr + kc * 32);
            #pragma unroll
            for (int nt4 = 0; nt4 < 4; nt4++) {
                uint32_t bf[4];
                ldsm4(bf, bAddrV[nt4] + bOff + kc * 32);
                mma8(O[nt4 * 2],     pf, bf[0], bf[1]);
                mma8(O[nt4 * 2 + 1], pf, bf[2], bf[3]);
            }
        }
    }

    float inv0 = 1.0f / li0, inv1 = 1.0f / li1;
    int row0 = b * Nseq + q0 + qr0 + g;
    #pragma unroll
    for (int e = 0; e < 8; e++) {
        int col = h * HDim + e * 8 + t * 2;
        float2 o0 = {round_tf32(O[e][0] * inv0), round_tf32(O[e][1] * inv0)};
        float2 o1 = {round_tf32(O[e][2] * inv1), round_tf32(O[e][3] * inv1)};
        *(float2*)&out[(size_t)row0 * Dm + col] = o0;
        *(float2*)&out[(size_t)(row0 + 8) * Dm + col] = o1;
    }
}

// ---------------- launch ----------------
extern "C" void kernel_launch(void* const* d_in, const int* in_sizes, int n_in,
                              void* d_out, int out_size)
{
    const float* x     = (const float*)d_in[0];
    const float* elev  = (const float*)d_in[1];
    const float* ln1g  = (const float*)d_in[2];
    const float* ln1b  = (const float*)d_in[3];
    const float* qkvw  = (const float*)d_in[4];
    const float* alpha = (const float*)d_in[5];
    const float* projw = (const float*)d_in[6];
    const float* projb = (const float*)d_in[7];
    const float* ln2g  = (const float*)d_in[8];
    const float* ln2b  = (const float*)d_in[9];
    const float* fc1w  = (const float*)d_in[10];
    const float* fc1b  = (const float*)d_in[11];
    const float* fc2w  = (const float*)d_in[12];
    const float* fc2b  = (const float*)d_in[13];
    float* out = (float*)d_out;

    float *ph, *pqkv, *pattn, *px1, *pact, *pwt, *pvt;
    cudaGetSymbolAddress((void**)&ph,    g_h);
    cudaGetSymbolAddress((void**)&pqkv,  g_qkv);
    cudaGetSymbolAddress((void**)&pattn, g_attn);
    cudaGetSymbolAddress((void**)&px1,   g_x1);
    cudaGetSymbolAddress((void**)&pact,  g_act);
    cudaGetSymbolAddress((void**)&pwt,   g_wt);
    cudaGetSymbolAddress((void**)&pvt,   g_vT);

    cudaFuncSetAttribute(attn_tc,
        cudaFuncAttributeMaxDynamicSharedMemorySize, ATT_BYTES);
    cudaFuncSetAttribute(tgemm<1536, 512, false, false, false, true>,
        cudaFuncAttributeMaxDynamicSharedMemorySize, GSMEM_B);
    cudaFuncSetAttribute(tgemm<512, 512, true, false, true, false>,
        cudaFuncAttributeMaxDynamicSharedMemorySize, GSMEM_B);
    cudaFuncSetAttribute(tgemm<2048, 512, true, true, false, true>,
        cudaFuncAttributeMaxDynamicSharedMemorySize, GSMEM_B);
    cudaFuncSetAttribute(tgemm<512, 2048, true, false, true, false>,
        cudaFuncAttributeMaxDynamicSharedMemorySize, GSMEM_B);

    // 0. weight transpose + tf32 round
    transpose_cvt<<<dim3(48, 16), dim3(32, 8)>>>(qkvw,  pwt + WT_QKV,  Dm,   3 * Dm);
    transpose_cvt<<<dim3(16, 16), dim3(32, 8)>>>(projw, pwt + WT_PROJ, Dm,   Dm);
    transpose_cvt<<<dim3(64, 16), dim3(32, 8)>>>(fc1w,  pwt + WT_FC1,  Dm,   MLPH);
    transpose_cvt<<<dim3(16, 64), dim3(32, 8)>>>(fc2w,  pwt + WT_FC2,  MLPH, Dm);

    // 1. LN1
    ln_kernel<<<ROWS, 128>>>(x, ln1g, ln1b, ph);
    // 2. qkv (ROUND=true)
    tgemm<1536, 512, false, false, false, true><<<dim3(12, 64), 128, GSMEM_B>>>(
        ph, pwt + WT_QKV, nullptr, nullptr, pqkv);
    // 2b. V transpose
    vtrans_kernel<<<dim3(64, 2, 32), dim3(32, 8)>>>(pqkv, pvt);
    // 3. attention
    attn_tc<<<dim3(Nseq / 128, Bsz * Hh), 256, ATT_BYTES>>>(
        pqkv, pvt, elev, alpha, pattn);
    // 4. x1 = x + attn @ proj_w + proj_b
    tgemm<512, 512, true, false, true, false><<<dim3(4, 64), 128, GSMEM_B>>>(
        pattn, pwt + WT_PROJ, projb, x, px1);
    // 5. LN2
    ln_kernel<<<ROWS, 128>>>(px1, ln2g, ln2b, ph);
    // 6. act = gelu(h2 @ fc1_w + fc1_b)
    tgemm<2048, 512, true, true, false, true><<<dim3(16, 64), 128, GSMEM_B>>>(
        ph, pwt + WT_FC1, fc1b, nullptr, pact);
    // 7. out = x1 + act @ fc2_w + fc2_b
    tgemm<512, 2048, true, false, true, false><<<dim3(4, 64), 128, GSMEM_B>>>(
        pact, pwt + WT_FC2, fc2b, px1, out);
}